// round 7
// baseline (speedup 1.0000x reference)
#include <cuda_runtime.h>
#include <cuda_bf16.h>
#include <math.h>
#include <stdint.h>

// Problem constants (recursive_index=0 -> G=8)
#define BB 8
#define NN 4096
#define CC 512
#define GG 8
#define HH 8
#define DH 64
#define LL 512

// Scratch (device globals; no cudaMalloc allowed)
__device__ __nv_bfloat16 g_x_hi[(size_t)BB * NN * CC];        // [32768,512]
__device__ __nv_bfloat16 g_x_lo[(size_t)BB * NN * CC];
__device__ __nv_bfloat16 g_qkv_hi[(size_t)BB * NN * 3 * CC];  // [32768,1536]
__device__ __nv_bfloat16 g_qkv_lo[(size_t)BB * NN * 3 * CC];
__device__ __nv_bfloat16 g_att_hi[(size_t)BB * NN * CC];      // [32768,512]
__device__ __nv_bfloat16 g_att_lo[(size_t)BB * NN * CC];
__device__ __nv_bfloat16 g_wq_hi[(size_t)CC * 3 * CC];        // [512,1536] (K,N)
__device__ __nv_bfloat16 g_wq_lo[(size_t)CC * 3 * CC];
__device__ __nv_bfloat16 g_wp_hi[(size_t)CC * CC];
__device__ __nv_bfloat16 g_wp_lo[(size_t)CC * CC];

// ---------------------------------------------------------------------------
// Helpers
// ---------------------------------------------------------------------------
__device__ __forceinline__ uint32_t smem_u32(const void* p) {
    uint32_t a;
    asm("{ .reg .u64 t; cvta.to.shared.u64 t, %1; cvt.u32.u64 %0, t; }" : "=r"(a) : "l"(p));
    return a;
}

#define LDM_X4(r, a) \
    asm volatile("ldmatrix.sync.aligned.m8n8.x4.shared.b16 {%0,%1,%2,%3}, [%4];" \
        : "=r"((r)[0]), "=r"((r)[1]), "=r"((r)[2]), "=r"((r)[3]) : "r"(a))

#define LDM_X4T(r, a) \
    asm volatile("ldmatrix.sync.aligned.m8n8.x4.trans.shared.b16 {%0,%1,%2,%3}, [%4];" \
        : "=r"((r)[0]), "=r"((r)[1]), "=r"((r)[2]), "=r"((r)[3]) : "r"(a))

#define MMA16816(c, a, b0, b1) \
    asm volatile("mma.sync.aligned.m16n8k16.row.col.f32.bf16.bf16.f32 " \
        "{%0,%1,%2,%3}, {%4,%5,%6,%7}, {%8,%9}, {%0,%1,%2,%3};" \
        : "+f"((c)[0]), "+f"((c)[1]), "+f"((c)[2]), "+f"((c)[3]) \
        : "r"((a)[0]), "r"((a)[1]), "r"((a)[2]), "r"((a)[3]), "r"(b0), "r"(b1))

#define CP16(dst, src) \
    asm volatile("cp.async.ca.shared.global [%0], [%1], 16;" :: "r"(dst), "l"(src))
#define CP_COMMIT() asm volatile("cp.async.commit_group;")
#define CP_WAIT0() asm volatile("cp.async.wait_group 0;")
#define CP_WAIT1() asm volatile("cp.async.wait_group 1;")
#define CP_WAIT2() asm volatile("cp.async.wait_group 2;")

__device__ __forceinline__ uint32_t pk(__nv_bfloat162 v) {
    return *reinterpret_cast<uint32_t*>(&v);
}
__device__ __forceinline__ void split2(float a, float b, uint32_t& hi, uint32_t& lo) {
    __nv_bfloat162 h = __floats2bfloat162_rn(a, b);
    __nv_bfloat162 l = __floats2bfloat162_rn(a - __bfloat162float(h.x),
                                             b - __bfloat162float(h.y));
    hi = pk(h); lo = pk(l);
}

// ---------------------------------------------------------------------------
// Split fp32 -> bf16 hi/lo (weights and x)
// ---------------------------------------------------------------------------
__global__ void splitw_kernel(const float* __restrict__ W,
                              __nv_bfloat16* __restrict__ hi,
                              __nv_bfloat16* __restrict__ lo, int total) {
    int idx = blockIdx.x * blockDim.x + threadIdx.x;
    if (idx >= total) return;
    float v = W[idx];
    __nv_bfloat16 h = __float2bfloat16_rn(v);
    hi[idx] = h;
    lo[idx] = __float2bfloat16_rn(v - __bfloat162float(h));
}

__global__ void splitx_kernel(const float* __restrict__ X,
                              __nv_bfloat16* __restrict__ hi,
                              __nv_bfloat16* __restrict__ lo) {
    int idx = blockIdx.x * blockDim.x + threadIdx.x;   // float4 index
    float4 v = *(const float4*)(X + (size_t)idx * 4);
    uint32_t h0, l0, h1, l1;
    split2(v.x, v.y, h0, l0);
    split2(v.z, v.w, h1, l1);
    uint2 hh; hh.x = h0; hh.y = h1;
    uint2 ll; ll.x = l0; ll.y = l1;
    *(uint2*)(hi + (size_t)idx * 4) = hh;
    *(uint2*)(lo + (size_t)idx * 4) = ll;
}

// ---------------------------------------------------------------------------
// All-bf16 HMMA x3 GEMM, cp.async 3-stage pipeline, ONE sync per chunk.
// C[M,N] = (Ah+Al)[M,K] @ (Bh+Bl)[K,N] (3-term), + bias.
// CTA 128x128, BK=32, 8 warps (2x4 of 64x32), 2 CTAs/SM.
// Stage layout (bytes, bf16 strides: A row 40, B row 136):
//   Ah 0..10240, Al 10240..20480, Bh 20480..29184, Bl 29184..37888
// ---------------------------------------------------------------------------
#define PSA 40
#define PSB 136
#define PS_AL 10240
#define PS_BH 20480
#define PS_BL 29184
#define PSS   37888
#define PGSM_TOTAL (3 * PSS)     // 113664 -> 2 CTAs/SM

__global__ __launch_bounds__(256, 2) void gemm_bf3_kernel(
    const __nv_bfloat16* __restrict__ Ahi, const __nv_bfloat16* __restrict__ Alo,
    const __nv_bfloat16* __restrict__ Bhi, const __nv_bfloat16* __restrict__ Blo,
    const float* __restrict__ bias, float* __restrict__ C,
    __nv_bfloat16* __restrict__ Chi, __nv_bfloat16* __restrict__ Clo,
    int M, int N, int K)
{
    extern __shared__ char sm[];
    const uint32_t sb = smem_u32(sm);
    const int tid = threadIdx.x;
    const int wid = tid >> 5, lane = tid & 31;
    const int wm = wid >> 2, wn = wid & 3;
    const int gid = lane >> 2, tig = lane & 3;
    const int m0 = blockIdx.y * 128, n0 = blockIdx.x * 128;

    const int a_row = lane & 15;
    const int a_col = (lane >> 4) * 8;
    const int b_krow = lane & 15;
    const int b_ncol = (lane & 16) ? 8 : 0;

    // cp.async mapping (per stage, per split: A 512x16B, B 512x16B)
    const int ar = tid >> 2, aq = tid & 3;          // +256 -> ar+64
    const int br = tid >> 4, bq = tid & 15;         // +256 -> br+16

    auto load_stage = [&](int c, int buf) {
        const uint32_t s0 = sb + buf * PSS;
        const int k0 = c * 32;
        #pragma unroll
        for (int i = 0; i < 2; ++i) {
            int r = ar + 64 * i;
            size_t ga = (size_t)(m0 + r) * K + k0 + aq * 8;
            uint32_t d = s0 + r * (PSA * 2) + aq * 16;
            CP16(d, Ahi + ga);
            CP16(d + PS_AL, Alo + ga);
        }
        #pragma unroll
        for (int i = 0; i < 2; ++i) {
            int r = br + 16 * i;
            size_t gb = (size_t)(k0 + r) * N + n0 + bq * 8;
            uint32_t d = s0 + PS_BH + r * (PSB * 2) + bq * 16;
            CP16(d, Bhi + gb);
            CP16(d + (PS_BL - PS_BH), Blo + gb);
        }
        CP_COMMIT();
    };

    float acc[4][4][4];
    #pragma unroll
    for (int i = 0; i < 4; i++)
        #pragma unroll
        for (int j = 0; j < 4; j++)
            #pragma unroll
            for (int t = 0; t < 4; t++) acc[i][j][t] = 0.f;

    const int NC = K >> 5;   // 32-wide chunks (16 for K=512)
    load_stage(0, 0);
    load_stage(1, 1);

    for (int c = 0; c < NC; ++c) {
        // All warps finished reading buffer (c-1)%3 -> safe to refill it.
        __syncthreads();
        if (c + 2 < NC) load_stage(c + 2, (c + 2) % 3);
        // Ensure chunk c has landed; chunks c+1, c+2 may remain in flight.
        if (c + 3 <= NC) { CP_WAIT2(); }
        else if (c + 2 == NC) { CP_WAIT1(); }
        else { CP_WAIT0(); }

        const uint32_t s0 = sb + (c % 3) * PSS;
        #pragma unroll
        for (int ks = 0; ks < 2; ++ks) {
            uint32_t bh[2][4], bl[2][4], af[4][4];
            #pragma unroll
            for (int p = 0; p < 2; ++p) {
                uint32_t ba = s0 + PS_BH
                    + (uint32_t)((ks * 16 + b_krow) * PSB + wn * 32 + p * 16 + b_ncol) * 2;
                LDM_X4T(bh[p], ba);
                LDM_X4T(bl[p], ba + (PS_BL - PS_BH));
            }
            #pragma unroll
            for (int i = 0; i < 4; ++i) {
                uint32_t aa = s0
                    + (uint32_t)((wm * 64 + i * 16 + a_row) * PSA + ks * 16 + a_col) * 2;
                LDM_X4(af[i], aa);
            }
            #pragma unroll
            for (int i = 0; i < 4; ++i)
                #pragma unroll
                for (int j = 0; j < 4; ++j) {
                    int p = j >> 1, q2 = (j & 1) * 2;
                    MMA16816(acc[i][j], af[i], bh[p][q2], bh[p][q2 + 1]);
                    MMA16816(acc[i][j], af[i], bl[p][q2], bl[p][q2 + 1]);
                }
            #pragma unroll
            for (int i = 0; i < 4; ++i) {
                uint32_t aa = s0 + PS_AL
                    + (uint32_t)((wm * 64 + i * 16 + a_row) * PSA + ks * 16 + a_col) * 2;
                LDM_X4(af[i], aa);
            }
            #pragma unroll
            for (int i = 0; i < 4; ++i)
                #pragma unroll
                for (int j = 0; j < 4; ++j) {
                    int p = j >> 1, q2 = (j & 1) * 2;
                    MMA16816(acc[i][j], af[i], bh[p][q2], bh[p][q2 + 1]);
                }
        }
    }

    #pragma unroll
    for (int i = 0; i < 4; ++i) {
        int r0 = m0 + wm * 64 + i * 16 + gid;
        #pragma unroll
        for (int j = 0; j < 4; ++j) {
            int cc = n0 + wn * 32 + j * 8 + 2 * tig;
            float bx = 0.f, by = 0.f;
            if (bias) { bx = bias[cc]; by = bias[cc + 1]; }
            float v0 = acc[i][j][0] + bx, v1 = acc[i][j][1] + by;
            float v2 = acc[i][j][2] + bx, v3 = acc[i][j][3] + by;
            if (Chi) {
                uint32_t h0, l0, h1, l1;
                split2(v0, v1, h0, l0);
                split2(v2, v3, h1, l1);
                *(uint32_t*)&Chi[(size_t)r0 * N + cc] = h0;
                *(uint32_t*)&Clo[(size_t)r0 * N + cc] = l0;
                *(uint32_t*)&Chi[(size_t)(r0 + 8) * N + cc] = h1;
                *(uint32_t*)&Clo[(size_t)(r0 + 8) * N + cc] = l1;
            } else {
                *(float2*)&C[(size_t)r0 * N + cc] = make_float2(v0, v1);
                *(float2*)&C[(size_t)(r0 + 8) * N + cc] = make_float2(v2, v3);
            }
        }
    }
}

// ---------------------------------------------------------------------------
// Tensorized flash attention (HMMA bf16x3). Epilogue writes bf16 hi/lo.
// ---------------------------------------------------------------------------
#define AT_QH 0
#define AT_QL 18432
#define AT_KV 36864
#define AT_KVB 36864
#define ATSM_TOTAL (AT_KV + 2 * AT_KVB)   // 110592

__global__ __launch_bounds__(256) void attn_mma_kernel()
{
    extern __shared__ char sm[];
    const uint32_t sb = smem_u32(sm);
    const int tid = threadIdx.x;
    const int w = tid >> 5, lane = tid & 31;
    const int gid = lane >> 2, tig = lane & 3;
    const int bgh = blockIdx.y;
    const int h = bgh & 7;
    const int g = (bgh >> 3) & 7;
    const int b = bgh >> 6;
    const int t0 = b * NN + g * LL;
    const int qrow0 = blockIdx.x * 128;
    const float scale = 0.125f;

    const int a_row = lane & 15;
    const int a_col = (lane >> 4) * 8;
    const int k_nrow = (lane & 7) + ((lane & 16) ? 8 : 0);
    const int k_kcol = (lane & 8) ? 8 : 0;
    const int v_krow = lane & 15;
    const int v_ncol = (lane & 16) ? 8 : 0;

    #pragma unroll
    for (int i = 0; i < 4; ++i) {
        int t = tid + 256 * i;
        int r = t >> 3, dq = t & 7;
        size_t go = (size_t)(t0 + qrow0 + r) * 1536 + h * 64 + dq * 8;
        uint32_t d = sb + AT_QH + r * 144 + dq * 16;
        CP16(d, g_qkv_hi + go);
        CP16(d + AT_QL, g_qkv_lo + go);
    }
    #pragma unroll
    for (int i = 0; i < 2; ++i) {
        int t = tid + 256 * i;
        int r = t >> 3, dq = t & 7;
        size_t go = (size_t)(t0 + r) * 1536 + 512 + h * 64 + dq * 8;
        uint32_t d = sb + AT_KV + r * 144 + dq * 16;
        CP16(d, g_qkv_hi + go);
        CP16(d + 9216, g_qkv_lo + go);
        CP16(d + 18432, g_qkv_hi + go + 512);
        CP16(d + 27648, g_qkv_lo + go + 512);
    }
    CP_COMMIT();

    float s_o[8][4];
    float rmax0 = -1e30f, rmax1 = -1e30f, rsum0 = 0.f, rsum1 = 0.f;
    #pragma unroll
    for (int j = 0; j < 8; ++j)
        #pragma unroll
        for (int t = 0; t < 4; ++t) s_o[j][t] = 0.f;

    for (int c = 0; c < 8; ++c) {
        if (c < 7) {
            int buf = (c + 1) & 1;
            #pragma unroll
            for (int i = 0; i < 2; ++i) {
                int t = tid + 256 * i;
                int r = t >> 3, dq = t & 7;
                size_t go = (size_t)(t0 + (c + 1) * 64 + r) * 1536 + 512 + h * 64 + dq * 8;
                uint32_t d = sb + AT_KV + buf * AT_KVB + r * 144 + dq * 16;
                CP16(d, g_qkv_hi + go);
                CP16(d + 9216, g_qkv_lo + go);
                CP16(d + 18432, g_qkv_hi + go + 512);
                CP16(d + 27648, g_qkv_lo + go + 512);
            }
            CP_COMMIT();
            CP_WAIT1();
        } else {
            CP_WAIT0();
        }
        __syncthreads();

        const uint32_t kb = sb + AT_KV + (c & 1) * AT_KVB;
        const uint32_t vb = kb + 18432;

        float s_[8][4];
        #pragma unroll
        for (int j = 0; j < 8; ++j)
            #pragma unroll
            for (int t = 0; t < 4; ++t) s_[j][t] = 0.f;

        #pragma unroll
        for (int ks = 0; ks < 4; ++ks) {
            uint32_t qh[4], ql[4], kh[4][4], kl[4][4];
            uint32_t qa = sb + AT_QH + (uint32_t)((w * 16 + a_row) * 72 + ks * 16 + a_col) * 2;
            LDM_X4(qh, qa);
            LDM_X4(ql, qa + AT_QL);
            #pragma unroll
            for (int p = 0; p < 4; ++p) {
                uint32_t ka = kb + (uint32_t)((p * 16 + k_nrow) * 72 + ks * 16 + k_kcol) * 2;
                LDM_X4(kh[p], ka);
                LDM_X4(kl[p], ka + 9216);
            }
            #pragma unroll
            for (int j = 0; j < 8; ++j) {
                int p = j >> 1, q2 = (j & 1) * 2;
                MMA16816(s_[j], qh, kh[p][q2], kh[p][q2 + 1]);
                MMA16816(s_[j], qh, kl[p][q2], kl[p][q2 + 1]);
                MMA16816(s_[j], ql, kh[p][q2], kh[p][q2 + 1]);
            }
        }

        float m0 = -1e30f, m1 = -1e30f;
        #pragma unroll
        for (int j = 0; j < 8; ++j) {
            s_[j][0] *= scale; s_[j][1] *= scale;
            s_[j][2] *= scale; s_[j][3] *= scale;
            m0 = fmaxf(m0, fmaxf(s_[j][0], s_[j][1]));
            m1 = fmaxf(m1, fmaxf(s_[j][2], s_[j][3]));
        }
        m0 = fmaxf(m0, __shfl_xor_sync(0xffffffffu, m0, 1));
        m0 = fmaxf(m0, __shfl_xor_sync(0xffffffffu, m0, 2));
        m1 = fmaxf(m1, __shfl_xor_sync(0xffffffffu, m1, 1));
        m1 = fmaxf(m1, __shfl_xor_sync(0xffffffffu, m1, 2));
        float nm0 = fmaxf(rmax0, m0), nm1 = fmaxf(rmax1, m1);
        float al0 = __expf(rmax0 - nm0), al1 = __expf(rmax1 - nm1);
        float cs0 = 0.f, cs1 = 0.f;
        #pragma unroll
        for (int j = 0; j < 8; ++j) {
            s_[j][0] = __expf(s_[j][0] - nm0);
            s_[j][1] = __expf(s_[j][1] - nm0);
            s_[j][2] = __expf(s_[j][2] - nm1);
            s_[j][3] = __expf(s_[j][3] - nm1);
            cs0 += s_[j][0] + s_[j][1];
            cs1 += s_[j][2] + s_[j][3];
        }
        cs0 += __shfl_xor_sync(0xffffffffu, cs0, 1);
        cs0 += __shfl_xor_sync(0xffffffffu, cs0, 2);
        cs1 += __shfl_xor_sync(0xffffffffu, cs1, 1);
        cs1 += __shfl_xor_sync(0xffffffffu, cs1, 2);
        rsum0 = rsum0 * al0 + cs0;
        rsum1 = rsum1 * al1 + cs1;
        rmax0 = nm0; rmax1 = nm1;
        #pragma unroll
        for (int j = 0; j < 8; ++j) {
            s_o[j][0] *= al0; s_o[j][1] *= al0;
            s_o[j][2] *= al1; s_o[j][3] *= al1;
        }

        #pragma unroll
        for (int kf = 0; kf < 4; ++kf) {
            uint32_t ph[4], pl[4], vh[4][4], vl[4][4];
            int ja = 2 * kf, jb = 2 * kf + 1;
            split2(s_[ja][0], s_[ja][1], ph[0], pl[0]);
            split2(s_[ja][2], s_[ja][3], ph[1], pl[1]);
            split2(s_[jb][0], s_[jb][1], ph[2], pl[2]);
            split2(s_[jb][2], s_[jb][3], ph[3], pl[3]);
            #pragma unroll
            for (int p = 0; p < 4; ++p) {
                uint32_t va = vb + (uint32_t)((kf * 16 + v_krow) * 72 + p * 16 + v_ncol) * 2;
                LDM_X4T(vh[p], va);
                LDM_X4T(vl[p], va + 9216);
            }
            #pragma unroll
            for (int j = 0; j < 8; ++j) {
                int p = j >> 1, q2 = (j & 1) * 2;
                MMA16816(s_o[j], ph, vh[p][q2], vh[p][q2 + 1]);
                MMA16816(s_o[j], ph, vl[p][q2], vl[p][q2 + 1]);
                MMA16816(s_o[j], pl, vh[p][q2], vh[p][q2 + 1]);
            }
        }
        __syncthreads();
    }

    float inv0 = 1.f / rsum0, inv1 = 1.f / rsum1;
    const int r0 = t0 + qrow0 + w * 16 + gid;
    #pragma unroll
    for (int j = 0; j < 8; ++j) {
        int cc = h * 64 + j * 8 + 2 * tig;
        uint32_t h0, l0, h1, l1;
        split2(s_o[j][0] * inv0, s_o[j][1] * inv0, h0, l0);
        split2(s_o[j][2] * inv1, s_o[j][3] * inv1, h1, l1);
        *(uint32_t*)&g_att_hi[(size_t)r0 * CC + cc] = h0;
        *(uint32_t*)&g_att_lo[(size_t)r0 * CC + cc] = l0;
        *(uint32_t*)&g_att_hi[(size_t)(r0 + 8) * CC + cc] = h1;
        *(uint32_t*)&g_att_lo[(size_t)(r0 + 8) * CC + cc] = l1;
    }
}

// ---------------------------------------------------------------------------
extern "C" void kernel_launch(void* const* d_in, const int* in_sizes, int n_in,
                              void* d_out, int out_size)
{
    const float* x      = (const float*)d_in[0];
    const float* W_qkv  = (const float*)d_in[1];
    const float* W_proj = (const float*)d_in[2];
    const float* b_proj = (const float*)d_in[3];
    float* out = (float*)d_out;

    __nv_bfloat16 *xh, *xl, *qkvh, *qkvl, *ath, *atl, *wqh, *wql, *wph, *wpl;
    cudaGetSymbolAddress((void**)&xh, g_x_hi);
    cudaGetSymbolAddress((void**)&xl, g_x_lo);
    cudaGetSymbolAddress((void**)&qkvh, g_qkv_hi);
    cudaGetSymbolAddress((void**)&qkvl, g_qkv_lo);
    cudaGetSymbolAddress((void**)&ath, g_att_hi);
    cudaGetSymbolAddress((void**)&atl, g_att_lo);
    cudaGetSymbolAddress((void**)&wqh, g_wq_hi);
    cudaGetSymbolAddress((void**)&wql, g_wq_lo);
    cudaGetSymbolAddress((void**)&wph, g_wp_hi);
    cudaGetSymbolAddress((void**)&wpl, g_wp_lo);

    cudaFuncSetAttribute(gemm_bf3_kernel,
                         cudaFuncAttributeMaxDynamicSharedMemorySize, PGSM_TOTAL);
    cudaFuncSetAttribute(attn_mma_kernel,
                         cudaFuncAttributeMaxDynamicSharedMemorySize, ATSM_TOTAL);

    const int M = BB * NN;   // 32768

    // 0) Splits
    splitw_kernel<<<(3 * CC * CC + 255) / 256, 256>>>(W_qkv, wqh, wql, 3 * CC * CC);
    splitw_kernel<<<(CC * CC + 255) / 256, 256>>>(W_proj, wph, wpl, CC * CC);
    splitx_kernel<<<(M * CC / 4) / 256, 256>>>(x, xh, xl);

    // 1) qkv = x @ W_qkv  (bf16x3, 3-stage pipeline), split bf16 out
    {
        dim3 grid((3 * CC) / 128, M / 128);
        gemm_bf3_kernel<<<grid, 256, PGSM_TOTAL>>>(xh, xl, wqh, wql, nullptr,
                                                   nullptr, qkvh, qkvl,
                                                   M, 3 * CC, CC);
    }

    // 2) tensorized flash attention -> split bf16 out
    {
        dim3 grid(LL / 128, BB * GG * HH);
        attn_mma_kernel<<<grid, 256, ATSM_TOTAL>>>();
    }

    // 3) out = att @ W_proj + b_proj  (bf16x3, 3-stage pipeline), fp32 out
    {
        dim3 grid(CC / 128, M / 128);
        gemm_bf3_kernel<<<grid, 256, PGSM_TOTAL>>>(ath, atl, wph, wpl, b_proj,
                                                   out, nullptr, nullptr,
                                                   M, CC, CC);
    }
}

// round 8
// speedup vs baseline: 1.4959x; 1.4959x over previous
#include <cuda_runtime.h>
#include <cuda_fp16.h>
#include <math.h>
#include <stdint.h>

// Problem constants (recursive_index=0 -> G=8)
#define BB 8
#define NN 4096
#define CC 512
#define GG 8
#define HH 8
#define DH 64
#define LL 512

// Scratch (device globals; no cudaMalloc allowed)
__device__ __half g_x_hi[(size_t)BB * NN * CC];        // [32768,512]
__device__ __half g_x_lo[(size_t)BB * NN * CC];
__device__ __half g_qkv_hi[(size_t)BB * NN * 3 * CC];  // [32768,1536]
__device__ __half g_qkv_lo[(size_t)BB * NN * 3 * CC];
__device__ __half g_att_hi[(size_t)BB * NN * CC];      // [32768,512]
__device__ __half g_att_lo[(size_t)BB * NN * CC];
__device__ __half g_wq[(size_t)CC * 3 * CC];           // [512,1536] (K,N)
__device__ __half g_wp[(size_t)CC * CC];               // [512,512]

// ---------------------------------------------------------------------------
// Helpers
// ---------------------------------------------------------------------------
__device__ __forceinline__ uint32_t smem_u32(const void* p) {
    uint32_t a;
    asm("{ .reg .u64 t; cvta.to.shared.u64 t, %1; cvt.u32.u64 %0, t; }" : "=r"(a) : "l"(p));
    return a;
}

#define LDM_X4(r, a) \
    asm volatile("ldmatrix.sync.aligned.m8n8.x4.shared.b16 {%0,%1,%2,%3}, [%4];" \
        : "=r"((r)[0]), "=r"((r)[1]), "=r"((r)[2]), "=r"((r)[3]) : "r"(a))

#define LDM_X4T(r, a) \
    asm volatile("ldmatrix.sync.aligned.m8n8.x4.trans.shared.b16 {%0,%1,%2,%3}, [%4];" \
        : "=r"((r)[0]), "=r"((r)[1]), "=r"((r)[2]), "=r"((r)[3]) : "r"(a))

#define MMA16816(c, a, b0, b1) \
    asm volatile("mma.sync.aligned.m16n8k16.row.col.f32.f16.f16.f32 " \
        "{%0,%1,%2,%3}, {%4,%5,%6,%7}, {%8,%9}, {%0,%1,%2,%3};" \
        : "+f"((c)[0]), "+f"((c)[1]), "+f"((c)[2]), "+f"((c)[3]) \
        : "r"((a)[0]), "r"((a)[1]), "r"((a)[2]), "r"((a)[3]), "r"(b0), "r"(b1))

#define CP16(dst, src) \
    asm volatile("cp.async.ca.shared.global [%0], [%1], 16;" :: "r"(dst), "l"(src))
#define CP_COMMIT() asm volatile("cp.async.commit_group;")
#define CP_WAIT0() asm volatile("cp.async.wait_group 0;")
#define CP_WAIT1() asm volatile("cp.async.wait_group 1;")

__device__ __forceinline__ uint32_t pkh(__half2 v) {
    return *reinterpret_cast<uint32_t*>(&v);
}
// pack two floats into fp16x2 (hi) and fp16x2 of remainders (lo)
__device__ __forceinline__ void split2h(float a, float b, uint32_t& hi, uint32_t& lo) {
    __half2 h = __floats2half2_rn(a, b);
    __half2 l = __floats2half2_rn(a - __half2float(h.x), b - __half2float(h.y));
    hi = pkh(h); lo = pkh(l);
}

// ---------------------------------------------------------------------------
// Weight round: fp32 -> fp16 (single term). x: fp32 -> fp16 hi/lo.
// ---------------------------------------------------------------------------
__global__ void roundw_kernel(const float* __restrict__ W,
                              __half* __restrict__ hi, int total) {
    int idx = blockIdx.x * blockDim.x + threadIdx.x;
    if (idx >= total) return;
    hi[idx] = __float2half_rn(W[idx]);
}

__global__ void splitx_kernel(const float* __restrict__ X,
                              __half* __restrict__ hi,
                              __half* __restrict__ lo) {
    int idx = blockIdx.x * blockDim.x + threadIdx.x;   // float4 index
    float4 v = *(const float4*)(X + (size_t)idx * 4);
    uint32_t h0, l0, h1, l1;
    split2h(v.x, v.y, h0, l0);
    split2h(v.z, v.w, h1, l1);
    uint2 hh; hh.x = h0; hh.y = h1;
    uint2 ll; ll.x = l0; ll.y = l1;
    *(uint2*)(hi + (size_t)idx * 4) = hh;
    *(uint2*)(lo + (size_t)idx * 4) = ll;
}

// ---------------------------------------------------------------------------
// fp16x2 HMMA GEMM, cp.async 2-stage pipeline (R6-proven schedule).
// C[M,N] = (Ah+Al)[M,K] @ Bh[K,N] (2-term), + bias.
// CTA 128x128, BK=32, 8 warps (2x4 of 64x32).
// Stage layout (bytes, fp16 strides: A row 40, B row 136):
//   Ah 0..10240, Al 10240..20480, Bh 20480..29184
// ---------------------------------------------------------------------------
#define PSA 40
#define PSB 136
#define PS_AL 10240
#define PS_BH 20480
#define PSS   29184
#define PGSM_TOTAL (2 * PSS)     // 58368

__global__ __launch_bounds__(256, 2) void gemm_h2_kernel(
    const __half* __restrict__ Ahi, const __half* __restrict__ Alo,
    const __half* __restrict__ Bh,
    const float* __restrict__ bias, float* __restrict__ C,
    __half* __restrict__ Chi, __half* __restrict__ Clo,
    int M, int N, int K)
{
    extern __shared__ char sm[];
    const uint32_t sb = smem_u32(sm);
    const int tid = threadIdx.x;
    const int wid = tid >> 5, lane = tid & 31;
    const int wm = wid >> 2, wn = wid & 3;
    const int gid = lane >> 2, tig = lane & 3;
    const int m0 = blockIdx.y * 128, n0 = blockIdx.x * 128;

    const int a_row = lane & 15;
    const int a_col = (lane >> 4) * 8;
    const int b_krow = lane & 15;
    const int b_ncol = (lane & 16) ? 8 : 0;

    const int ar = tid >> 2, aq = tid & 3;          // A: 128 rows x 4 16B-chunks
    const int br = tid >> 4, bq = tid & 15;         // B: 32 rows x 16 16B-chunks

    auto load_stage = [&](int c, int buf) {
        const uint32_t s0 = sb + buf * PSS;
        const int k0 = c * 32;
        #pragma unroll
        for (int i = 0; i < 2; ++i) {
            int r = ar + 64 * i;
            size_t ga = (size_t)(m0 + r) * K + k0 + aq * 8;
            uint32_t d = s0 + r * (PSA * 2) + aq * 16;
            CP16(d, Ahi + ga);
            CP16(d + PS_AL, Alo + ga);
        }
        #pragma unroll
        for (int i = 0; i < 2; ++i) {
            int r = br + 16 * i;
            size_t gb = (size_t)(k0 + r) * N + n0 + bq * 8;
            uint32_t d = s0 + PS_BH + r * (PSB * 2) + bq * 16;
            CP16(d, Bh + gb);
        }
        CP_COMMIT();
    };

    float acc[4][4][4];
    #pragma unroll
    for (int i = 0; i < 4; i++)
        #pragma unroll
        for (int j = 0; j < 4; j++)
            #pragma unroll
            for (int t = 0; t < 4; t++) acc[i][j][t] = 0.f;

    const int NC = K >> 5;
    load_stage(0, 0);

    for (int c = 0; c < NC; ++c) {
        if (c + 1 < NC) { load_stage(c + 1, (c + 1) & 1); CP_WAIT1(); }
        else            { CP_WAIT0(); }
        __syncthreads();

        const uint32_t s0 = sb + (c & 1) * PSS;
        #pragma unroll
        for (int ks = 0; ks < 2; ++ks) {
            uint32_t bh[2][4], af[4][4];
            #pragma unroll
            for (int p = 0; p < 2; ++p) {
                uint32_t ba = s0 + PS_BH
                    + (uint32_t)((ks * 16 + b_krow) * PSB + wn * 32 + p * 16 + b_ncol) * 2;
                LDM_X4T(bh[p], ba);
            }
            #pragma unroll
            for (int i = 0; i < 4; ++i) {
                uint32_t aa = s0
                    + (uint32_t)((wm * 64 + i * 16 + a_row) * PSA + ks * 16 + a_col) * 2;
                LDM_X4(af[i], aa);
            }
            #pragma unroll
            for (int i = 0; i < 4; ++i)
                #pragma unroll
                for (int j = 0; j < 4; ++j) {
                    int p = j >> 1, q2 = (j & 1) * 2;
                    MMA16816(acc[i][j], af[i], bh[p][q2], bh[p][q2 + 1]);
                }
            #pragma unroll
            for (int i = 0; i < 4; ++i) {
                uint32_t aa = s0 + PS_AL
                    + (uint32_t)((wm * 64 + i * 16 + a_row) * PSA + ks * 16 + a_col) * 2;
                LDM_X4(af[i], aa);
            }
            #pragma unroll
            for (int i = 0; i < 4; ++i)
                #pragma unroll
                for (int j = 0; j < 4; ++j) {
                    int p = j >> 1, q2 = (j & 1) * 2;
                    MMA16816(acc[i][j], af[i], bh[p][q2], bh[p][q2 + 1]);
                }
        }
        __syncthreads();   // protect buffer reuse by next iteration's cp.async
    }

    #pragma unroll
    for (int i = 0; i < 4; ++i) {
        int r0 = m0 + wm * 64 + i * 16 + gid;
        #pragma unroll
        for (int j = 0; j < 4; ++j) {
            int cc = n0 + wn * 32 + j * 8 + 2 * tig;
            float bx = 0.f, by = 0.f;
            if (bias) { bx = bias[cc]; by = bias[cc + 1]; }
            float v0 = acc[i][j][0] + bx, v1 = acc[i][j][1] + by;
            float v2 = acc[i][j][2] + bx, v3 = acc[i][j][3] + by;
            if (Chi) {
                uint32_t h0, l0, h1, l1;
                split2h(v0, v1, h0, l0);
                split2h(v2, v3, h1, l1);
                *(uint32_t*)&Chi[(size_t)r0 * N + cc] = h0;
                *(uint32_t*)&Clo[(size_t)r0 * N + cc] = l0;
                *(uint32_t*)&Chi[(size_t)(r0 + 8) * N + cc] = h1;
                *(uint32_t*)&Clo[(size_t)(r0 + 8) * N + cc] = l1;
            } else {
                *(float2*)&C[(size_t)r0 * N + cc] = make_float2(v0, v1);
                *(float2*)&C[(size_t)(r0 + 8) * N + cc] = make_float2(v2, v3);
            }
        }
    }
}

// ---------------------------------------------------------------------------
// Tensorized flash attention, fp16x2:
// S = (Qh+Ql) Kh^T,  O += (Ph+Pl) Vh.  K and V single fp16 term.
// Smem: Qh [128][72]@0, Ql @18432; KV double-buffered @36864,
//   per buffer (18432B): Kh [64][72] @+0, Vh [64][72] @+9216.
// ---------------------------------------------------------------------------
#define AT_QH 0
#define AT_QL 18432
#define AT_KV 36864
#define AT_KVB 18432
#define ATSM_TOTAL (AT_KV + 2 * AT_KVB)   // 73728

__global__ __launch_bounds__(256) void attn_mma_kernel()
{
    extern __shared__ char sm[];
    const uint32_t sb = smem_u32(sm);
    const int tid = threadIdx.x;
    const int w = tid >> 5, lane = tid & 31;
    const int gid = lane >> 2, tig = lane & 3;
    const int bgh = blockIdx.y;
    const int h = bgh & 7;
    const int g = (bgh >> 3) & 7;
    const int b = bgh >> 6;
    const int t0 = b * NN + g * LL;
    const int qrow0 = blockIdx.x * 128;
    const float scale = 0.125f;

    const int a_row = lane & 15;
    const int a_col = (lane >> 4) * 8;
    const int k_nrow = (lane & 7) + ((lane & 16) ? 8 : 0);
    const int k_kcol = (lane & 8) ? 8 : 0;
    const int v_krow = lane & 15;
    const int v_ncol = (lane & 16) ? 8 : 0;

    // Q hi/lo: 128 rows x 64 fp16 = 8 x 16B per row
    #pragma unroll
    for (int i = 0; i < 4; ++i) {
        int t = tid + 256 * i;
        int r = t >> 3, dq = t & 7;
        size_t go = (size_t)(t0 + qrow0 + r) * 1536 + h * 64 + dq * 8;
        uint32_t d = sb + AT_QH + r * 144 + dq * 16;
        CP16(d, g_qkv_hi + go);
        CP16(d + AT_QL, g_qkv_lo + go);
    }
    // KV chunk 0: K hi + V hi only
    #pragma unroll
    for (int i = 0; i < 2; ++i) {
        int t = tid + 256 * i;
        int r = t >> 3, dq = t & 7;
        size_t go = (size_t)(t0 + r) * 1536 + 512 + h * 64 + dq * 8;
        uint32_t d = sb + AT_KV + r * 144 + dq * 16;
        CP16(d, g_qkv_hi + go);             // Kh
        CP16(d + 9216, g_qkv_hi + go + 512);  // Vh
    }
    CP_COMMIT();

    float s_o[8][4];
    float rmax0 = -1e30f, rmax1 = -1e30f, rsum0 = 0.f, rsum1 = 0.f;
    #pragma unroll
    for (int j = 0; j < 8; ++j)
        #pragma unroll
        for (int t = 0; t < 4; ++t) s_o[j][t] = 0.f;

    for (int c = 0; c < 8; ++c) {
        if (c < 7) {
            int buf = (c + 1) & 1;
            #pragma unroll
            for (int i = 0; i < 2; ++i) {
                int t = tid + 256 * i;
                int r = t >> 3, dq = t & 7;
                size_t go = (size_t)(t0 + (c + 1) * 64 + r) * 1536 + 512 + h * 64 + dq * 8;
                uint32_t d = sb + AT_KV + buf * AT_KVB + r * 144 + dq * 16;
                CP16(d, g_qkv_hi + go);
                CP16(d + 9216, g_qkv_hi + go + 512);
            }
            CP_COMMIT();
            CP_WAIT1();
        } else {
            CP_WAIT0();
        }
        __syncthreads();

        const uint32_t kb = sb + AT_KV + (c & 1) * AT_KVB;
        const uint32_t vb = kb + 9216;

        float s_[8][4];
        #pragma unroll
        for (int j = 0; j < 8; ++j)
            #pragma unroll
            for (int t = 0; t < 4; ++t) s_[j][t] = 0.f;

        #pragma unroll
        for (int ks = 0; ks < 4; ++ks) {
            uint32_t qh[4], ql[4], kh[4][4];
            uint32_t qa = sb + AT_QH + (uint32_t)((w * 16 + a_row) * 72 + ks * 16 + a_col) * 2;
            LDM_X4(qh, qa);
            LDM_X4(ql, qa + AT_QL);
            #pragma unroll
            for (int p = 0; p < 4; ++p) {
                uint32_t ka = kb + (uint32_t)((p * 16 + k_nrow) * 72 + ks * 16 + k_kcol) * 2;
                LDM_X4(kh[p], ka);
            }
            #pragma unroll
            for (int j = 0; j < 8; ++j) {
                int p = j >> 1, q2 = (j & 1) * 2;
                MMA16816(s_[j], qh, kh[p][q2], kh[p][q2 + 1]);
                MMA16816(s_[j], ql, kh[p][q2], kh[p][q2 + 1]);
            }
        }

        float m0 = -1e30f, m1 = -1e30f;
        #pragma unroll
        for (int j = 0; j < 8; ++j) {
            s_[j][0] *= scale; s_[j][1] *= scale;
            s_[j][2] *= scale; s_[j][3] *= scale;
            m0 = fmaxf(m0, fmaxf(s_[j][0], s_[j][1]));
            m1 = fmaxf(m1, fmaxf(s_[j][2], s_[j][3]));
        }
        m0 = fmaxf(m0, __shfl_xor_sync(0xffffffffu, m0, 1));
        m0 = fmaxf(m0, __shfl_xor_sync(0xffffffffu, m0, 2));
        m1 = fmaxf(m1, __shfl_xor_sync(0xffffffffu, m1, 1));
        m1 = fmaxf(m1, __shfl_xor_sync(0xffffffffu, m1, 2));
        float nm0 = fmaxf(rmax0, m0), nm1 = fmaxf(rmax1, m1);
        float al0 = __expf(rmax0 - nm0), al1 = __expf(rmax1 - nm1);
        float cs0 = 0.f, cs1 = 0.f;
        #pragma unroll
        for (int j = 0; j < 8; ++j) {
            s_[j][0] = __expf(s_[j][0] - nm0);
            s_[j][1] = __expf(s_[j][1] - nm0);
            s_[j][2] = __expf(s_[j][2] - nm1);
            s_[j][3] = __expf(s_[j][3] - nm1);
            cs0 += s_[j][0] + s_[j][1];
            cs1 += s_[j][2] + s_[j][3];
        }
        cs0 += __shfl_xor_sync(0xffffffffu, cs0, 1);
        cs0 += __shfl_xor_sync(0xffffffffu, cs0, 2);
        cs1 += __shfl_xor_sync(0xffffffffu, cs1, 1);
        cs1 += __shfl_xor_sync(0xffffffffu, cs1, 2);
        rsum0 = rsum0 * al0 + cs0;
        rsum1 = rsum1 * al1 + cs1;
        rmax0 = nm0; rmax1 = nm1;
        #pragma unroll
        for (int j = 0; j < 8; ++j) {
            s_o[j][0] *= al0; s_o[j][1] *= al0;
            s_o[j][2] *= al1; s_o[j][3] *= al1;
        }

        #pragma unroll
        for (int kf = 0; kf < 4; ++kf) {
            uint32_t ph[4], pl[4], vh[4][4];
            int ja = 2 * kf, jb = 2 * kf + 1;
            split2h(s_[ja][0], s_[ja][1], ph[0], pl[0]);
            split2h(s_[ja][2], s_[ja][3], ph[1], pl[1]);
            split2h(s_[jb][0], s_[jb][1], ph[2], pl[2]);
            split2h(s_[jb][2], s_[jb][3], ph[3], pl[3]);
            #pragma unroll
            for (int p = 0; p < 4; ++p) {
                uint32_t va = vb + (uint32_t)((kf * 16 + v_krow) * 72 + p * 16 + v_ncol) * 2;
                LDM_X4T(vh[p], va);
            }
            #pragma unroll
            for (int j = 0; j < 8; ++j) {
                int p = j >> 1, q2 = (j & 1) * 2;
                MMA16816(s_o[j], ph, vh[p][q2], vh[p][q2 + 1]);
                MMA16816(s_o[j], pl, vh[p][q2], vh[p][q2 + 1]);
            }
        }
        __syncthreads();
    }

    // normalize + write fp16 hi/lo, [token][512], col = h*64 + d
    float inv0 = 1.f / rsum0, inv1 = 1.f / rsum1;
    const int r0 = t0 + qrow0 + w * 16 + gid;
    #pragma unroll
    for (int j = 0; j < 8; ++j) {
        int cc = h * 64 + j * 8 + 2 * tig;
        uint32_t h0, l0, h1, l1;
        split2h(s_o[j][0] * inv0, s_o[j][1] * inv0, h0, l0);
        split2h(s_o[j][2] * inv1, s_o[j][3] * inv1, h1, l1);
        *(uint32_t*)&g_att_hi[(size_t)r0 * CC + cc] = h0;
        *(uint32_t*)&g_att_lo[(size_t)r0 * CC + cc] = l0;
        *(uint32_t*)&g_att_hi[(size_t)(r0 + 8) * CC + cc] = h1;
        *(uint32_t*)&g_att_lo[(size_t)(r0 + 8) * CC + cc] = l1;
    }
}

// ---------------------------------------------------------------------------
extern "C" void kernel_launch(void* const* d_in, const int* in_sizes, int n_in,
                              void* d_out, int out_size)
{
    const float* x      = (const float*)d_in[0];
    const float* W_qkv  = (const float*)d_in[1];
    const float* W_proj = (const float*)d_in[2];
    const float* b_proj = (const float*)d_in[3];
    float* out = (float*)d_out;

    __half *xh, *xl, *qkvh, *qkvl, *ath, *atl, *wq, *wp;
    cudaGetSymbolAddress((void**)&xh, g_x_hi);
    cudaGetSymbolAddress((void**)&xl, g_x_lo);
    cudaGetSymbolAddress((void**)&qkvh, g_qkv_hi);
    cudaGetSymbolAddress((void**)&qkvl, g_qkv_lo);
    cudaGetSymbolAddress((void**)&ath, g_att_hi);
    cudaGetSymbolAddress((void**)&atl, g_att_lo);
    cudaGetSymbolAddress((void**)&wq, g_wq);
    cudaGetSymbolAddress((void**)&wp, g_wp);

    cudaFuncSetAttribute(gemm_h2_kernel,
                         cudaFuncAttributeMaxDynamicSharedMemorySize, PGSM_TOTAL);
    cudaFuncSetAttribute(attn_mma_kernel,
                         cudaFuncAttributeMaxDynamicSharedMemorySize, ATSM_TOTAL);

    const int M = BB * NN;   // 32768

    // 0) Weight round (fp16 single) + x split (fp16 hi/lo)
    roundw_kernel<<<(3 * CC * CC + 255) / 256, 256>>>(W_qkv, wq, 3 * CC * CC);
    roundw_kernel<<<(CC * CC + 255) / 256, 256>>>(W_proj, wp, CC * CC);
    splitx_kernel<<<(M * CC / 4) / 256, 256>>>(x, xh, xl);

    // 1) qkv = x @ W_qkv  (fp16x2), split fp16 out
    {
        dim3 grid((3 * CC) / 128, M / 128);
        gemm_h2_kernel<<<grid, 256, PGSM_TOTAL>>>(xh, xl, wq, nullptr,
                                                  nullptr, qkvh, qkvl,
                                                  M, 3 * CC, CC);
    }

    // 2) tensorized flash attention -> split fp16 out
    {
        dim3 grid(LL / 128, BB * GG * HH);
        attn_mma_kernel<<<grid, 256, ATSM_TOTAL>>>();
    }

    // 3) out = att @ W_proj + b_proj  (fp16x2), fp32 out
    {
        dim3 grid(CC / 128, M / 128);
        gemm_h2_kernel<<<grid, 256, PGSM_TOTAL>>>(ath, atl, wp, b_proj,
                                                  out, nullptr, nullptr,
                                                  M, CC, CC);
    }
}

// round 9
// speedup vs baseline: 1.5807x; 1.0567x over previous
#include <cuda_runtime.h>
#include <cuda_fp16.h>
#include <math.h>
#include <stdint.h>

// Problem constants (recursive_index=0 -> G=8)
#define BB 8
#define NN 4096
#define CC 512
#define GG 8
#define HH 8
#define DH 64
#define LL 512

// Scratch (device globals; no cudaMalloc allowed)
__device__ __half g_x_hi[(size_t)BB * NN * CC];        // [32768,512]
__device__ __half g_x_lo[(size_t)BB * NN * CC];
__device__ __half g_qkv_hi[(size_t)BB * NN * 3 * CC];  // [32768,1536]
__device__ __half g_qkv_lo[(size_t)BB * NN * 3 * CC];  // only Q cols (0..511) used
__device__ __half g_att_hi[(size_t)BB * NN * CC];      // [32768,512]
__device__ __half g_att_lo[(size_t)BB * NN * CC];
__device__ __half g_wq[(size_t)CC * 3 * CC];           // [512,1536] (K,N)
__device__ __half g_wp[(size_t)CC * CC];               // [512,512]

// ---------------------------------------------------------------------------
// Helpers
// ---------------------------------------------------------------------------
__device__ __forceinline__ uint32_t smem_u32(const void* p) {
    uint32_t a;
    asm("{ .reg .u64 t; cvta.to.shared.u64 t, %1; cvt.u32.u64 %0, t; }" : "=r"(a) : "l"(p));
    return a;
}

#define LDM_X4(r, a) \
    asm volatile("ldmatrix.sync.aligned.m8n8.x4.shared.b16 {%0,%1,%2,%3}, [%4];" \
        : "=r"((r)[0]), "=r"((r)[1]), "=r"((r)[2]), "=r"((r)[3]) : "r"(a))

#define LDM_X4T(r, a) \
    asm volatile("ldmatrix.sync.aligned.m8n8.x4.trans.shared.b16 {%0,%1,%2,%3}, [%4];" \
        : "=r"((r)[0]), "=r"((r)[1]), "=r"((r)[2]), "=r"((r)[3]) : "r"(a))

#define MMA16816(c, a, b0, b1) \
    asm volatile("mma.sync.aligned.m16n8k16.row.col.f32.f16.f16.f32 " \
        "{%0,%1,%2,%3}, {%4,%5,%6,%7}, {%8,%9}, {%0,%1,%2,%3};" \
        : "+f"((c)[0]), "+f"((c)[1]), "+f"((c)[2]), "+f"((c)[3]) \
        : "r"((a)[0]), "r"((a)[1]), "r"((a)[2]), "r"((a)[3]), "r"(b0), "r"(b1))

// .cg: bypass L1 (all staged data is single-read; avoid L1 pollution)
#define CP16(dst, src) \
    asm volatile("cp.async.cg.shared.global [%0], [%1], 16;" :: "r"(dst), "l"(src))
#define CP_COMMIT() asm volatile("cp.async.commit_group;")
#define CP_WAIT0() asm volatile("cp.async.wait_group 0;")
#define CP_WAIT1() asm volatile("cp.async.wait_group 1;")

__device__ __forceinline__ uint32_t pkh(__half2 v) {
    return *reinterpret_cast<uint32_t*>(&v);
}
__device__ __forceinline__ void split2h(float a, float b, uint32_t& hi, uint32_t& lo) {
    __half2 h = __floats2half2_rn(a, b);
    __half2 l = __floats2half2_rn(a - __half2float(h.x), b - __half2float(h.y));
    hi = pkh(h); lo = pkh(l);
}

// ---------------------------------------------------------------------------
// Weight round: fp32 -> fp16. x: fp32 -> fp16 hi/lo.
// ---------------------------------------------------------------------------
__global__ void roundw_kernel(const float* __restrict__ W,
                              __half* __restrict__ hi, int total) {
    int idx = blockIdx.x * blockDim.x + threadIdx.x;
    if (idx >= total) return;
    hi[idx] = __float2half_rn(W[idx]);
}

__global__ void splitx_kernel(const float* __restrict__ X,
                              __half* __restrict__ hi,
                              __half* __restrict__ lo) {
    int idx = blockIdx.x * blockDim.x + threadIdx.x;   // float4 index
    float4 v = *(const float4*)(X + (size_t)idx * 4);
    uint32_t h0, l0, h1, l1;
    split2h(v.x, v.y, h0, l0);
    split2h(v.z, v.w, h1, l1);
    uint2 hh; hh.x = h0; hh.y = h1;
    uint2 ll; ll.x = l0; ll.y = l1;
    *(uint2*)(hi + (size_t)idx * 4) = hh;
    *(uint2*)(lo + (size_t)idx * 4) = ll;
}

// ---------------------------------------------------------------------------
// fp16x2 HMMA GEMM, cp.async 2-stage pipeline, BK=64.
// C[M,N] = (Ah+Al)[M,K] @ Bh[K,N] (2-term), + bias.
// CTA 128x128, 8 warps (2x4 of 64x32).
// Stage layout (bytes, fp16 row strides: A 72, B 136):
//   Ah 0..18432, Al 18432..36864, Bh 36864..54272
// ---------------------------------------------------------------------------
#define PSA 72
#define PSB 136
#define PS_AL 18432
#define PS_BH 36864
#define PSS   54272
#define PGSM_TOTAL (2 * PSS)     // 108544 -> 2 CTAs/SM

__global__ __launch_bounds__(256, 2) void gemm_h2_kernel(
    const __half* __restrict__ Ahi, const __half* __restrict__ Alo,
    const __half* __restrict__ Bh,
    const float* __restrict__ bias, float* __restrict__ C,
    __half* __restrict__ Chi, __half* __restrict__ Clo, int lo_ncols,
    int M, int N, int K)
{
    extern __shared__ char sm[];
    const uint32_t sb = smem_u32(sm);
    const int tid = threadIdx.x;
    const int wid = tid >> 5, lane = tid & 31;
    const int wm = wid >> 2, wn = wid & 3;
    const int gid = lane >> 2, tig = lane & 3;
    const int m0 = blockIdx.y * 128, n0 = blockIdx.x * 128;

    const int a_row = lane & 15;
    const int a_col = (lane >> 4) * 8;
    const int b_krow = lane & 15;
    const int b_ncol = (lane & 16) ? 8 : 0;

    // cp.async mapping: A per term 128 rows x 8 16B-chunks (1024), B 64 x 16 (1024)
    const int ar = tid >> 3, aq = tid & 7;
    const int br = tid >> 4, bq = tid & 15;

    auto load_stage = [&](int c, int buf) {
        const uint32_t s0 = sb + buf * PSS;
        const int k0 = c * 64;
        #pragma unroll
        for (int i = 0; i < 4; ++i) {
            int r = ar + 32 * i;
            size_t ga = (size_t)(m0 + r) * K + k0 + aq * 8;
            uint32_t d = s0 + r * (PSA * 2) + aq * 16;
            CP16(d, Ahi + ga);
            CP16(d + PS_AL, Alo + ga);
        }
        #pragma unroll
        for (int i = 0; i < 4; ++i) {
            int r = br + 16 * i;
            size_t gb = (size_t)(k0 + r) * N + n0 + bq * 8;
            uint32_t d = s0 + PS_BH + r * (PSB * 2) + bq * 16;
            CP16(d, Bh + gb);
        }
        CP_COMMIT();
    };

    float acc[4][4][4];
    #pragma unroll
    for (int i = 0; i < 4; i++)
        #pragma unroll
        for (int j = 0; j < 4; j++)
            #pragma unroll
            for (int t = 0; t < 4; t++) acc[i][j][t] = 0.f;

    const int NC = K >> 6;   // 64-wide chunks (8 for K=512)
    load_stage(0, 0);

    for (int c = 0; c < NC; ++c) {
        if (c + 1 < NC) { load_stage(c + 1, (c + 1) & 1); CP_WAIT1(); }
        else            { CP_WAIT0(); }
        __syncthreads();

        const uint32_t s0 = sb + (c & 1) * PSS;
        #pragma unroll
        for (int ks = 0; ks < 4; ++ks) {
            uint32_t bh[2][4], af[4][4];
            #pragma unroll
            for (int p = 0; p < 2; ++p) {
                uint32_t ba = s0 + PS_BH
                    + (uint32_t)((ks * 16 + b_krow) * PSB + wn * 32 + p * 16 + b_ncol) * 2;
                LDM_X4T(bh[p], ba);
            }
            #pragma unroll
            for (int i = 0; i < 4; ++i) {
                uint32_t aa = s0
                    + (uint32_t)((wm * 64 + i * 16 + a_row) * PSA + ks * 16 + a_col) * 2;
                LDM_X4(af[i], aa);
            }
            #pragma unroll
            for (int i = 0; i < 4; ++i)
                #pragma unroll
                for (int j = 0; j < 4; ++j) {
                    int p = j >> 1, q2 = (j & 1) * 2;
                    MMA16816(acc[i][j], af[i], bh[p][q2], bh[p][q2 + 1]);
                }
            #pragma unroll
            for (int i = 0; i < 4; ++i) {
                uint32_t aa = s0 + PS_AL
                    + (uint32_t)((wm * 64 + i * 16 + a_row) * PSA + ks * 16 + a_col) * 2;
                LDM_X4(af[i], aa);
            }
            #pragma unroll
            for (int i = 0; i < 4; ++i)
                #pragma unroll
                for (int j = 0; j < 4; ++j) {
                    int p = j >> 1, q2 = (j & 1) * 2;
                    MMA16816(acc[i][j], af[i], bh[p][q2], bh[p][q2 + 1]);
                }
        }
        __syncthreads();   // protect buffer reuse by next iteration's cp.async
    }

    #pragma unroll
    for (int i = 0; i < 4; ++i) {
        int r0 = m0 + wm * 64 + i * 16 + gid;
        #pragma unroll
        for (int j = 0; j < 4; ++j) {
            int cc = n0 + wn * 32 + j * 8 + 2 * tig;
            float bx = 0.f, by = 0.f;
            if (bias) { bx = bias[cc]; by = bias[cc + 1]; }
            float v0 = acc[i][j][0] + bx, v1 = acc[i][j][1] + by;
            float v2 = acc[i][j][2] + bx, v3 = acc[i][j][3] + by;
            if (Chi) {
                uint32_t h0, l0, h1, l1;
                split2h(v0, v1, h0, l0);
                split2h(v2, v3, h1, l1);
                *(uint32_t*)&Chi[(size_t)r0 * N + cc] = h0;
                *(uint32_t*)&Chi[(size_t)(r0 + 8) * N + cc] = h1;
                if (cc < lo_ncols) {   // lo only consumed for Q columns
                    *(uint32_t*)&Clo[(size_t)r0 * N + cc] = l0;
                    *(uint32_t*)&Clo[(size_t)(r0 + 8) * N + cc] = l1;
                }
            } else {
                *(float2*)&C[(size_t)r0 * N + cc] = make_float2(v0, v1);
                *(float2*)&C[(size_t)(r0 + 8) * N + cc] = make_float2(v2, v3);
            }
        }
    }
}

// ---------------------------------------------------------------------------
// Tensorized flash attention, fp16x2 (unchanged arithmetic from R8).
// ---------------------------------------------------------------------------
#define AT_QH 0
#define AT_QL 18432
#define AT_KV 36864
#define AT_KVB 18432
#define ATSM_TOTAL (AT_KV + 2 * AT_KVB)   // 73728

__global__ __launch_bounds__(256) void attn_mma_kernel()
{
    extern __shared__ char sm[];
    const uint32_t sb = smem_u32(sm);
    const int tid = threadIdx.x;
    const int w = tid >> 5, lane = tid & 31;
    const int gid = lane >> 2, tig = lane & 3;
    const int bgh = blockIdx.y;
    const int h = bgh & 7;
    const int g = (bgh >> 3) & 7;
    const int b = bgh >> 6;
    const int t0 = b * NN + g * LL;
    const int qrow0 = blockIdx.x * 128;
    const float scale = 0.125f;

    const int a_row = lane & 15;
    const int a_col = (lane >> 4) * 8;
    const int k_nrow = (lane & 7) + ((lane & 16) ? 8 : 0);
    const int k_kcol = (lane & 8) ? 8 : 0;
    const int v_krow = lane & 15;
    const int v_ncol = (lane & 16) ? 8 : 0;

    #pragma unroll
    for (int i = 0; i < 4; ++i) {
        int t = tid + 256 * i;
        int r = t >> 3, dq = t & 7;
        size_t go = (size_t)(t0 + qrow0 + r) * 1536 + h * 64 + dq * 8;
        uint32_t d = sb + AT_QH + r * 144 + dq * 16;
        CP16(d, g_qkv_hi + go);
        CP16(d + AT_QL, g_qkv_lo + go);
    }
    #pragma unroll
    for (int i = 0; i < 2; ++i) {
        int t = tid + 256 * i;
        int r = t >> 3, dq = t & 7;
        size_t go = (size_t)(t0 + r) * 1536 + 512 + h * 64 + dq * 8;
        uint32_t d = sb + AT_KV + r * 144 + dq * 16;
        CP16(d, g_qkv_hi + go);
        CP16(d + 9216, g_qkv_hi + go + 512);
    }
    CP_COMMIT();

    float s_o[8][4];
    float rmax0 = -1e30f, rmax1 = -1e30f, rsum0 = 0.f, rsum1 = 0.f;
    #pragma unroll
    for (int j = 0; j < 8; ++j)
        #pragma unroll
        for (int t = 0; t < 4; ++t) s_o[j][t] = 0.f;

    for (int c = 0; c < 8; ++c) {
        if (c < 7) {
            int buf = (c + 1) & 1;
            #pragma unroll
            for (int i = 0; i < 2; ++i) {
                int t = tid + 256 * i;
                int r = t >> 3, dq = t & 7;
                size_t go = (size_t)(t0 + (c + 1) * 64 + r) * 1536 + 512 + h * 64 + dq * 8;
                uint32_t d = sb + AT_KV + buf * AT_KVB + r * 144 + dq * 16;
                CP16(d, g_qkv_hi + go);
                CP16(d + 9216, g_qkv_hi + go + 512);
            }
            CP_COMMIT();
            CP_WAIT1();
        } else {
            CP_WAIT0();
        }
        __syncthreads();

        const uint32_t kb = sb + AT_KV + (c & 1) * AT_KVB;
        const uint32_t vb = kb + 9216;

        float s_[8][4];
        #pragma unroll
        for (int j = 0; j < 8; ++j)
            #pragma unroll
            for (int t = 0; t < 4; ++t) s_[j][t] = 0.f;

        #pragma unroll
        for (int ks = 0; ks < 4; ++ks) {
            uint32_t qh[4], ql[4], kh[4][4];
            uint32_t qa = sb + AT_QH + (uint32_t)((w * 16 + a_row) * 72 + ks * 16 + a_col) * 2;
            LDM_X4(qh, qa);
            LDM_X4(ql, qa + AT_QL);
            #pragma unroll
            for (int p = 0; p < 4; ++p) {
                uint32_t ka = kb + (uint32_t)((p * 16 + k_nrow) * 72 + ks * 16 + k_kcol) * 2;
                LDM_X4(kh[p], ka);
            }
            #pragma unroll
            for (int j = 0; j < 8; ++j) {
                int p = j >> 1, q2 = (j & 1) * 2;
                MMA16816(s_[j], qh, kh[p][q2], kh[p][q2 + 1]);
                MMA16816(s_[j], ql, kh[p][q2], kh[p][q2 + 1]);
            }
        }

        float m0 = -1e30f, m1 = -1e30f;
        #pragma unroll
        for (int j = 0; j < 8; ++j) {
            s_[j][0] *= scale; s_[j][1] *= scale;
            s_[j][2] *= scale; s_[j][3] *= scale;
            m0 = fmaxf(m0, fmaxf(s_[j][0], s_[j][1]));
            m1 = fmaxf(m1, fmaxf(s_[j][2], s_[j][3]));
        }
        m0 = fmaxf(m0, __shfl_xor_sync(0xffffffffu, m0, 1));
        m0 = fmaxf(m0, __shfl_xor_sync(0xffffffffu, m0, 2));
        m1 = fmaxf(m1, __shfl_xor_sync(0xffffffffu, m1, 1));
        m1 = fmaxf(m1, __shfl_xor_sync(0xffffffffu, m1, 2));
        float nm0 = fmaxf(rmax0, m0), nm1 = fmaxf(rmax1, m1);
        float al0 = __expf(rmax0 - nm0), al1 = __expf(rmax1 - nm1);
        float cs0 = 0.f, cs1 = 0.f;
        #pragma unroll
        for (int j = 0; j < 8; ++j) {
            s_[j][0] = __expf(s_[j][0] - nm0);
            s_[j][1] = __expf(s_[j][1] - nm0);
            s_[j][2] = __expf(s_[j][2] - nm1);
            s_[j][3] = __expf(s_[j][3] - nm1);
            cs0 += s_[j][0] + s_[j][1];
            cs1 += s_[j][2] + s_[j][3];
        }
        cs0 += __shfl_xor_sync(0xffffffffu, cs0, 1);
        cs0 += __shfl_xor_sync(0xffffffffu, cs0, 2);
        cs1 += __shfl_xor_sync(0xffffffffu, cs1, 1);
        cs1 += __shfl_xor_sync(0xffffffffu, cs1, 2);
        rsum0 = rsum0 * al0 + cs0;
        rsum1 = rsum1 * al1 + cs1;
        rmax0 = nm0; rmax1 = nm1;
        #pragma unroll
        for (int j = 0; j < 8; ++j) {
            s_o[j][0] *= al0; s_o[j][1] *= al0;
            s_o[j][2] *= al1; s_o[j][3] *= al1;
        }

        #pragma unroll
        for (int kf = 0; kf < 4; ++kf) {
            uint32_t ph[4], pl[4], vh[4][4];
            int ja = 2 * kf, jb = 2 * kf + 1;
            split2h(s_[ja][0], s_[ja][1], ph[0], pl[0]);
            split2h(s_[ja][2], s_[ja][3], ph[1], pl[1]);
            split2h(s_[jb][0], s_[jb][1], ph[2], pl[2]);
            split2h(s_[jb][2], s_[jb][3], ph[3], pl[3]);
            #pragma unroll
            for (int p = 0; p < 4; ++p) {
                uint32_t va = vb + (uint32_t)((kf * 16 + v_krow) * 72 + p * 16 + v_ncol) * 2;
                LDM_X4T(vh[p], va);
            }
            #pragma unroll
            for (int j = 0; j < 8; ++j) {
                int p = j >> 1, q2 = (j & 1) * 2;
                MMA16816(s_o[j], ph, vh[p][q2], vh[p][q2 + 1]);
                MMA16816(s_o[j], pl, vh[p][q2], vh[p][q2 + 1]);
            }
        }
        __syncthreads();
    }

    float inv0 = 1.f / rsum0, inv1 = 1.f / rsum1;
    const int r0 = t0 + qrow0 + w * 16 + gid;
    #pragma unroll
    for (int j = 0; j < 8; ++j) {
        int cc = h * 64 + j * 8 + 2 * tig;
        uint32_t h0, l0, h1, l1;
        split2h(s_o[j][0] * inv0, s_o[j][1] * inv0, h0, l0);
        split2h(s_o[j][2] * inv1, s_o[j][3] * inv1, h1, l1);
        *(uint32_t*)&g_att_hi[(size_t)r0 * CC + cc] = h0;
        *(uint32_t*)&g_att_lo[(size_t)r0 * CC + cc] = l0;
        *(uint32_t*)&g_att_hi[(size_t)(r0 + 8) * CC + cc] = h1;
        *(uint32_t*)&g_att_lo[(size_t)(r0 + 8) * CC + cc] = l1;
    }
}

// ---------------------------------------------------------------------------
extern "C" void kernel_launch(void* const* d_in, const int* in_sizes, int n_in,
                              void* d_out, int out_size)
{
    const float* x      = (const float*)d_in[0];
    const float* W_qkv  = (const float*)d_in[1];
    const float* W_proj = (const float*)d_in[2];
    const float* b_proj = (const float*)d_in[3];
    float* out = (float*)d_out;

    __half *xh, *xl, *qkvh, *qkvl, *ath, *atl, *wq, *wp;
    cudaGetSymbolAddress((void**)&xh, g_x_hi);
    cudaGetSymbolAddress((void**)&xl, g_x_lo);
    cudaGetSymbolAddress((void**)&qkvh, g_qkv_hi);
    cudaGetSymbolAddress((void**)&qkvl, g_qkv_lo);
    cudaGetSymbolAddress((void**)&ath, g_att_hi);
    cudaGetSymbolAddress((void**)&atl, g_att_lo);
    cudaGetSymbolAddress((void**)&wq, g_wq);
    cudaGetSymbolAddress((void**)&wp, g_wp);

    cudaFuncSetAttribute(gemm_h2_kernel,
                         cudaFuncAttributeMaxDynamicSharedMemorySize, PGSM_TOTAL);
    cudaFuncSetAttribute(attn_mma_kernel,
                         cudaFuncAttributeMaxDynamicSharedMemorySize, ATSM_TOTAL);

    const int M = BB * NN;   // 32768

    // 0) Weight round (fp16 single) + x split (fp16 hi/lo)
    roundw_kernel<<<(3 * CC * CC + 255) / 256, 256>>>(W_qkv, wq, 3 * CC * CC);
    roundw_kernel<<<(CC * CC + 255) / 256, 256>>>(W_proj, wp, CC * CC);
    splitx_kernel<<<(M * CC / 4) / 256, 256>>>(x, xh, xl);

    // 1) qkv = x @ W_qkv  (fp16x2, BK=64), split fp16 out (lo only for Q cols)
    {
        dim3 grid((3 * CC) / 128, M / 128);
        gemm_h2_kernel<<<grid, 256, PGSM_TOTAL>>>(xh, xl, wq, nullptr,
                                                  nullptr, qkvh, qkvl, CC,
                                                  M, 3 * CC, CC);
    }

    // 2) tensorized flash attention -> split fp16 out
    {
        dim3 grid(LL / 128, BB * GG * HH);
        attn_mma_kernel<<<grid, 256, ATSM_TOTAL>>>();
    }

    // 3) out = att @ W_proj + b_proj  (fp16x2, BK=64), fp32 out
    {
        dim3 grid(CC / 128, M / 128);
        gemm_h2_kernel<<<grid, 256, PGSM_TOTAL>>>(ath, atl, wp, b_proj,
                                                  out, nullptr, nullptr, 0,
                                                  M, CC, CC);
    }
}

// round 10
// speedup vs baseline: 1.6838x; 1.0652x over previous
#include <cuda_runtime.h>
#include <cuda_fp16.h>
#include <math.h>
#include <stdint.h>

// Problem constants (recursive_index=0 -> G=8)
#define BB 8
#define NN 4096
#define CC 512
#define GG 8
#define HH 8
#define DH 64
#define LL 512

// Scratch (device globals; no cudaMalloc allowed)
__device__ __half g_x_hi[(size_t)BB * NN * CC];        // [32768,512]
__device__ __half g_x_lo[(size_t)BB * NN * CC];
__device__ __half g_qkv_hi[(size_t)BB * NN * 3 * CC];  // [32768,1536]
__device__ __half g_qkv_lo[(size_t)BB * NN * 3 * CC];  // only Q cols (0..511) used
__device__ __half g_att_hi[(size_t)BB * NN * CC];      // [32768,512]
__device__ __half g_att_lo[(size_t)BB * NN * CC];
__device__ __half g_wq[(size_t)CC * 3 * CC];           // [512,1536] (K,N)
__device__ __half g_wp[(size_t)CC * CC];               // [512,512]

// ---------------------------------------------------------------------------
// Helpers
// ---------------------------------------------------------------------------
__device__ __forceinline__ uint32_t smem_u32(const void* p) {
    uint32_t a;
    asm("{ .reg .u64 t; cvta.to.shared.u64 t, %1; cvt.u32.u64 %0, t; }" : "=r"(a) : "l"(p));
    return a;
}

#define LDM_X4(r, a) \
    asm volatile("ldmatrix.sync.aligned.m8n8.x4.shared.b16 {%0,%1,%2,%3}, [%4];" \
        : "=r"((r)[0]), "=r"((r)[1]), "=r"((r)[2]), "=r"((r)[3]) : "r"(a))

#define LDM_X4T(r, a) \
    asm volatile("ldmatrix.sync.aligned.m8n8.x4.trans.shared.b16 {%0,%1,%2,%3}, [%4];" \
        : "=r"((r)[0]), "=r"((r)[1]), "=r"((r)[2]), "=r"((r)[3]) : "r"(a))

#define MMA16816(c, a, b0, b1) \
    asm volatile("mma.sync.aligned.m16n8k16.row.col.f32.f16.f16.f32 " \
        "{%0,%1,%2,%3}, {%4,%5,%6,%7}, {%8,%9}, {%0,%1,%2,%3};" \
        : "+f"((c)[0]), "+f"((c)[1]), "+f"((c)[2]), "+f"((c)[3]) \
        : "r"((a)[0]), "r"((a)[1]), "r"((a)[2]), "r"((a)[3]), "r"(b0), "r"(b1))

// .cg: bypass L1 (all staged data is single-read)
#define CP16(dst, src) \
    asm volatile("cp.async.cg.shared.global [%0], [%1], 16;" :: "r"(dst), "l"(src))
#define CP_COMMIT() asm volatile("cp.async.commit_group;")
#define CP_WAIT0() asm volatile("cp.async.wait_group 0;")
#define CP_WAIT1() asm volatile("cp.async.wait_group 1;")

__device__ __forceinline__ uint32_t pkh(__half2 v) {
    return *reinterpret_cast<uint32_t*>(&v);
}
__device__ __forceinline__ void split2h(float a, float b, uint32_t& hi, uint32_t& lo) {
    __half2 h = __floats2half2_rn(a, b);
    __half2 l = __floats2half2_rn(a - __half2float(h.x), b - __half2float(h.y));
    hi = pkh(h); lo = pkh(l);
}

// ---------------------------------------------------------------------------
// Weight round: fp32 -> fp16. x: fp32 -> fp16 hi/lo.
// ---------------------------------------------------------------------------
__global__ void roundw_kernel(const float* __restrict__ W,
                              __half* __restrict__ hi, int total) {
    int idx = blockIdx.x * blockDim.x + threadIdx.x;
    if (idx >= total) return;
    hi[idx] = __float2half_rn(W[idx]);
}

__global__ void splitx_kernel(const float* __restrict__ X,
                              __half* __restrict__ hi,
                              __half* __restrict__ lo) {
    int idx = blockIdx.x * blockDim.x + threadIdx.x;   // float4 index
    float4 v = *(const float4*)(X + (size_t)idx * 4);
    uint32_t h0, l0, h1, l1;
    split2h(v.x, v.y, h0, l0);
    split2h(v.z, v.w, h1, l1);
    uint2 hh; hh.x = h0; hh.y = h1;
    uint2 ll; ll.x = l0; ll.y = l1;
    *(uint2*)(hi + (size_t)idx * 4) = hh;
    *(uint2*)(lo + (size_t)idx * 4) = ll;
}

// ---------------------------------------------------------------------------
// fp16x2 HMMA GEMM, cp.async 2-stage pipeline, BK=64 (R9-proven).
// C[M,N] = (Ah+Al)[M,K] @ Bh[K,N] (2-term), + bias.
// ---------------------------------------------------------------------------
#define PSA 72
#define PSB 136
#define PS_AL 18432
#define PS_BH 36864
#define PSS   54272
#define PGSM_TOTAL (2 * PSS)     // 108544 -> 2 CTAs/SM

__global__ __launch_bounds__(256, 2) void gemm_h2_kernel(
    const __half* __restrict__ Ahi, const __half* __restrict__ Alo,
    const __half* __restrict__ Bh,
    const float* __restrict__ bias, float* __restrict__ C,
    __half* __restrict__ Chi, __half* __restrict__ Clo, int lo_ncols,
    int M, int N, int K)
{
    extern __shared__ char sm[];
    const uint32_t sb = smem_u32(sm);
    const int tid = threadIdx.x;
    const int wid = tid >> 5, lane = tid & 31;
    const int wm = wid >> 2, wn = wid & 3;
    const int gid = lane >> 2, tig = lane & 3;
    const int m0 = blockIdx.y * 128, n0 = blockIdx.x * 128;

    const int a_row = lane & 15;
    const int a_col = (lane >> 4) * 8;
    const int b_krow = lane & 15;
    const int b_ncol = (lane & 16) ? 8 : 0;

    const int ar = tid >> 3, aq = tid & 7;
    const int br = tid >> 4, bq = tid & 15;

    auto load_stage = [&](int c, int buf) {
        const uint32_t s0 = sb + buf * PSS;
        const int k0 = c * 64;
        #pragma unroll
        for (int i = 0; i < 4; ++i) {
            int r = ar + 32 * i;
            size_t ga = (size_t)(m0 + r) * K + k0 + aq * 8;
            uint32_t d = s0 + r * (PSA * 2) + aq * 16;
            CP16(d, Ahi + ga);
            CP16(d + PS_AL, Alo + ga);
        }
        #pragma unroll
        for (int i = 0; i < 4; ++i) {
            int r = br + 16 * i;
            size_t gb = (size_t)(k0 + r) * N + n0 + bq * 8;
            uint32_t d = s0 + PS_BH + r * (PSB * 2) + bq * 16;
            CP16(d, Bh + gb);
        }
        CP_COMMIT();
    };

    float acc[4][4][4];
    #pragma unroll
    for (int i = 0; i < 4; i++)
        #pragma unroll
        for (int j = 0; j < 4; j++)
            #pragma unroll
            for (int t = 0; t < 4; t++) acc[i][j][t] = 0.f;

    const int NC = K >> 6;
    load_stage(0, 0);

    for (int c = 0; c < NC; ++c) {
        if (c + 1 < NC) { load_stage(c + 1, (c + 1) & 1); CP_WAIT1(); }
        else            { CP_WAIT0(); }
        __syncthreads();

        const uint32_t s0 = sb + (c & 1) * PSS;
        #pragma unroll
        for (int ks = 0; ks < 4; ++ks) {
            uint32_t bh[2][4], af[4][4];
            #pragma unroll
            for (int p = 0; p < 2; ++p) {
                uint32_t ba = s0 + PS_BH
                    + (uint32_t)((ks * 16 + b_krow) * PSB + wn * 32 + p * 16 + b_ncol) * 2;
                LDM_X4T(bh[p], ba);
            }
            #pragma unroll
            for (int i = 0; i < 4; ++i) {
                uint32_t aa = s0
                    + (uint32_t)((wm * 64 + i * 16 + a_row) * PSA + ks * 16 + a_col) * 2;
                LDM_X4(af[i], aa);
            }
            #pragma unroll
            for (int i = 0; i < 4; ++i)
                #pragma unroll
                for (int j = 0; j < 4; ++j) {
                    int p = j >> 1, q2 = (j & 1) * 2;
                    MMA16816(acc[i][j], af[i], bh[p][q2], bh[p][q2 + 1]);
                }
            #pragma unroll
            for (int i = 0; i < 4; ++i) {
                uint32_t aa = s0 + PS_AL
                    + (uint32_t)((wm * 64 + i * 16 + a_row) * PSA + ks * 16 + a_col) * 2;
                LDM_X4(af[i], aa);
            }
            #pragma unroll
            for (int i = 0; i < 4; ++i)
                #pragma unroll
                for (int j = 0; j < 4; ++j) {
                    int p = j >> 1, q2 = (j & 1) * 2;
                    MMA16816(acc[i][j], af[i], bh[p][q2], bh[p][q2 + 1]);
                }
        }
        __syncthreads();
    }

    #pragma unroll
    for (int i = 0; i < 4; ++i) {
        int r0 = m0 + wm * 64 + i * 16 + gid;
        #pragma unroll
        for (int j = 0; j < 4; ++j) {
            int cc = n0 + wn * 32 + j * 8 + 2 * tig;
            float bx = 0.f, by = 0.f;
            if (bias) { bx = bias[cc]; by = bias[cc + 1]; }
            float v0 = acc[i][j][0] + bx, v1 = acc[i][j][1] + by;
            float v2 = acc[i][j][2] + bx, v3 = acc[i][j][3] + by;
            if (Chi) {
                uint32_t h0, l0, h1, l1;
                split2h(v0, v1, h0, l0);
                split2h(v2, v3, h1, l1);
                *(uint32_t*)&Chi[(size_t)r0 * N + cc] = h0;
                *(uint32_t*)&Chi[(size_t)(r0 + 8) * N + cc] = h1;
                if (cc < lo_ncols) {
                    *(uint32_t*)&Clo[(size_t)r0 * N + cc] = l0;
                    *(uint32_t*)&Clo[(size_t)(r0 + 8) * N + cc] = l1;
                }
            } else {
                *(float2*)&C[(size_t)r0 * N + cc] = make_float2(v0, v1);
                *(float2*)&C[(size_t)(r0 + 8) * N + cc] = make_float2(v2, v3);
            }
        }
    }
}

// ---------------------------------------------------------------------------
// Tensorized flash attention, fp16:
// S = (Qh+Ql) Kh^T  (2-term),  O += Ph Vh  (1-term: P-lo dropped).
// ---------------------------------------------------------------------------
#define AT_QH 0
#define AT_QL 18432
#define AT_KV 36864
#define AT_KVB 18432
#define ATSM_TOTAL (AT_KV + 2 * AT_KVB)   // 73728

__global__ __launch_bounds__(256) void attn_mma_kernel()
{
    extern __shared__ char sm[];
    const uint32_t sb = smem_u32(sm);
    const int tid = threadIdx.x;
    const int w = tid >> 5, lane = tid & 31;
    const int gid = lane >> 2, tig = lane & 3;
    const int bgh = blockIdx.y;
    const int h = bgh & 7;
    const int g = (bgh >> 3) & 7;
    const int b = bgh >> 6;
    const int t0 = b * NN + g * LL;
    const int qrow0 = blockIdx.x * 128;
    const float scale = 0.125f;

    const int a_row = lane & 15;
    const int a_col = (lane >> 4) * 8;
    const int k_nrow = (lane & 7) + ((lane & 16) ? 8 : 0);
    const int k_kcol = (lane & 8) ? 8 : 0;
    const int v_krow = lane & 15;
    const int v_ncol = (lane & 16) ? 8 : 0;

    #pragma unroll
    for (int i = 0; i < 4; ++i) {
        int t = tid + 256 * i;
        int r = t >> 3, dq = t & 7;
        size_t go = (size_t)(t0 + qrow0 + r) * 1536 + h * 64 + dq * 8;
        uint32_t d = sb + AT_QH + r * 144 + dq * 16;
        CP16(d, g_qkv_hi + go);
        CP16(d + AT_QL, g_qkv_lo + go);
    }
    #pragma unroll
    for (int i = 0; i < 2; ++i) {
        int t = tid + 256 * i;
        int r = t >> 3, dq = t & 7;
        size_t go = (size_t)(t0 + r) * 1536 + 512 + h * 64 + dq * 8;
        uint32_t d = sb + AT_KV + r * 144 + dq * 16;
        CP16(d, g_qkv_hi + go);
        CP16(d + 9216, g_qkv_hi + go + 512);
    }
    CP_COMMIT();

    float s_o[8][4];
    float rmax0 = -1e30f, rmax1 = -1e30f, rsum0 = 0.f, rsum1 = 0.f;
    #pragma unroll
    for (int j = 0; j < 8; ++j)
        #pragma unroll
        for (int t = 0; t < 4; ++t) s_o[j][t] = 0.f;

    for (int c = 0; c < 8; ++c) {
        if (c < 7) {
            int buf = (c + 1) & 1;
            #pragma unroll
            for (int i = 0; i < 2; ++i) {
                int t = tid + 256 * i;
                int r = t >> 3, dq = t & 7;
                size_t go = (size_t)(t0 + (c + 1) * 64 + r) * 1536 + 512 + h * 64 + dq * 8;
                uint32_t d = sb + AT_KV + buf * AT_KVB + r * 144 + dq * 16;
                CP16(d, g_qkv_hi + go);
                CP16(d + 9216, g_qkv_hi + go + 512);
            }
            CP_COMMIT();
            CP_WAIT1();
        } else {
            CP_WAIT0();
        }
        __syncthreads();

        const uint32_t kb = sb + AT_KV + (c & 1) * AT_KVB;
        const uint32_t vb = kb + 9216;

        float s_[8][4];
        #pragma unroll
        for (int j = 0; j < 8; ++j)
            #pragma unroll
            for (int t = 0; t < 4; ++t) s_[j][t] = 0.f;

        #pragma unroll
        for (int ks = 0; ks < 4; ++ks) {
            uint32_t qh[4], ql[4], kh[4][4];
            uint32_t qa = sb + AT_QH + (uint32_t)((w * 16 + a_row) * 72 + ks * 16 + a_col) * 2;
            LDM_X4(qh, qa);
            LDM_X4(ql, qa + AT_QL);
            #pragma unroll
            for (int p = 0; p < 4; ++p) {
                uint32_t ka = kb + (uint32_t)((p * 16 + k_nrow) * 72 + ks * 16 + k_kcol) * 2;
                LDM_X4(kh[p], ka);
            }
            #pragma unroll
            for (int j = 0; j < 8; ++j) {
                int p = j >> 1, q2 = (j & 1) * 2;
                MMA16816(s_[j], qh, kh[p][q2], kh[p][q2 + 1]);
                MMA16816(s_[j], ql, kh[p][q2], kh[p][q2 + 1]);
            }
        }

        float m0 = -1e30f, m1 = -1e30f;
        #pragma unroll
        for (int j = 0; j < 8; ++j) {
            s_[j][0] *= scale; s_[j][1] *= scale;
            s_[j][2] *= scale; s_[j][3] *= scale;
            m0 = fmaxf(m0, fmaxf(s_[j][0], s_[j][1]));
            m1 = fmaxf(m1, fmaxf(s_[j][2], s_[j][3]));
        }
        m0 = fmaxf(m0, __shfl_xor_sync(0xffffffffu, m0, 1));
        m0 = fmaxf(m0, __shfl_xor_sync(0xffffffffu, m0, 2));
        m1 = fmaxf(m1, __shfl_xor_sync(0xffffffffu, m1, 1));
        m1 = fmaxf(m1, __shfl_xor_sync(0xffffffffu, m1, 2));
        float nm0 = fmaxf(rmax0, m0), nm1 = fmaxf(rmax1, m1);
        float al0 = __expf(rmax0 - nm0), al1 = __expf(rmax1 - nm1);
        float cs0 = 0.f, cs1 = 0.f;
        #pragma unroll
        for (int j = 0; j < 8; ++j) {
            s_[j][0] = __expf(s_[j][0] - nm0);
            s_[j][1] = __expf(s_[j][1] - nm0);
            s_[j][2] = __expf(s_[j][2] - nm1);
            s_[j][3] = __expf(s_[j][3] - nm1);
            cs0 += s_[j][0] + s_[j][1];
            cs1 += s_[j][2] + s_[j][3];
        }
        cs0 += __shfl_xor_sync(0xffffffffu, cs0, 1);
        cs0 += __shfl_xor_sync(0xffffffffu, cs0, 2);
        cs1 += __shfl_xor_sync(0xffffffffu, cs1, 1);
        cs1 += __shfl_xor_sync(0xffffffffu, cs1, 2);
        rsum0 = rsum0 * al0 + cs0;
        rsum1 = rsum1 * al1 + cs1;
        rmax0 = nm0; rmax1 = nm1;
        #pragma unroll
        for (int j = 0; j < 8; ++j) {
            s_o[j][0] *= al0; s_o[j][1] *= al0;
            s_o[j][2] *= al1; s_o[j][3] *= al1;
        }

        // ---- O += P @ V (single term; P-lo dropped) ----
        #pragma unroll
        for (int kf = 0; kf < 4; ++kf) {
            uint32_t ph[4], vh[4][4];
            int ja = 2 * kf, jb = 2 * kf + 1;
            ph[0] = pkh(__floats2half2_rn(s_[ja][0], s_[ja][1]));
            ph[1] = pkh(__floats2half2_rn(s_[ja][2], s_[ja][3]));
            ph[2] = pkh(__floats2half2_rn(s_[jb][0], s_[jb][1]));
            ph[3] = pkh(__floats2half2_rn(s_[jb][2], s_[jb][3]));
            #pragma unroll
            for (int p = 0; p < 4; ++p) {
                uint32_t va = vb + (uint32_t)((kf * 16 + v_krow) * 72 + p * 16 + v_ncol) * 2;
                LDM_X4T(vh[p], va);
            }
            #pragma unroll
            for (int j = 0; j < 8; ++j) {
                int p = j >> 1, q2 = (j & 1) * 2;
                MMA16816(s_o[j], ph, vh[p][q2], vh[p][q2 + 1]);
            }
        }
        __syncthreads();
    }

    float inv0 = 1.f / rsum0, inv1 = 1.f / rsum1;
    const int r0 = t0 + qrow0 + w * 16 + gid;
    #pragma unroll
    for (int j = 0; j < 8; ++j) {
        int cc = h * 64 + j * 8 + 2 * tig;
        uint32_t h0, l0, h1, l1;
        split2h(s_o[j][0] * inv0, s_o[j][1] * inv0, h0, l0);
        split2h(s_o[j][2] * inv1, s_o[j][3] * inv1, h1, l1);
        *(uint32_t*)&g_att_hi[(size_t)r0 * CC + cc] = h0;
        *(uint32_t*)&g_att_lo[(size_t)r0 * CC + cc] = l0;
        *(uint32_t*)&g_att_hi[(size_t)(r0 + 8) * CC + cc] = h1;
        *(uint32_t*)&g_att_lo[(size_t)(r0 + 8) * CC + cc] = l1;
    }
}

// ---------------------------------------------------------------------------
extern "C" void kernel_launch(void* const* d_in, const int* in_sizes, int n_in,
                              void* d_out, int out_size)
{
    const float* x      = (const float*)d_in[0];
    const float* W_qkv  = (const float*)d_in[1];
    const float* W_proj = (const float*)d_in[2];
    const float* b_proj = (const float*)d_in[3];
    float* out = (float*)d_out;

    __half *xh, *xl, *qkvh, *qkvl, *ath, *atl, *wq, *wp;
    cudaGetSymbolAddress((void**)&xh, g_x_hi);
    cudaGetSymbolAddress((void**)&xl, g_x_lo);
    cudaGetSymbolAddress((void**)&qkvh, g_qkv_hi);
    cudaGetSymbolAddress((void**)&qkvl, g_qkv_lo);
    cudaGetSymbolAddress((void**)&ath, g_att_hi);
    cudaGetSymbolAddress((void**)&atl, g_att_lo);
    cudaGetSymbolAddress((void**)&wq, g_wq);
    cudaGetSymbolAddress((void**)&wp, g_wp);

    cudaFuncSetAttribute(gemm_h2_kernel,
                         cudaFuncAttributeMaxDynamicSharedMemorySize, PGSM_TOTAL);
    cudaFuncSetAttribute(attn_mma_kernel,
                         cudaFuncAttributeMaxDynamicSharedMemorySize, ATSM_TOTAL);

    const int M = BB * NN;   // 32768

    // 0) Weight round (fp16 single) + x split (fp16 hi/lo)
    roundw_kernel<<<(3 * CC * CC + 255) / 256, 256>>>(W_qkv, wq, 3 * CC * CC);
    roundw_kernel<<<(CC * CC + 255) / 256, 256>>>(W_proj, wp, CC * CC);
    splitx_kernel<<<(M * CC / 4) / 256, 256>>>(x, xh, xl);

    // 1) qkv = x @ W_qkv  (fp16x2, BK=64), split fp16 out (lo only for Q cols)
    {
        dim3 grid((3 * CC) / 128, M / 128);
        gemm_h2_kernel<<<grid, 256, PGSM_TOTAL>>>(xh, xl, wq, nullptr,
                                                  nullptr, qkvh, qkvl, CC,
                                                  M, 3 * CC, CC);
    }

    // 2) tensorized flash attention -> split fp16 out
    {
        dim3 grid(LL / 128, BB * GG * HH);
        attn_mma_kernel<<<grid, 256, ATSM_TOTAL>>>();
    }

    // 3) out = att @ W_proj + b_proj  (fp16x2, BK=64), fp32 out
    {
        dim3 grid(CC / 128, M / 128);
        gemm_h2_kernel<<<grid, 256, PGSM_TOTAL>>>(ath, atl, wp, b_proj,
                                                  out, nullptr, nullptr, 0,
                                                  M, CC, CC);
    }
}

// round 11
// speedup vs baseline: 2.0363x; 1.2094x over previous
#include <cuda_runtime.h>
#include <cuda_fp16.h>
#include <math.h>
#include <stdint.h>

// Problem constants (recursive_index=0 -> G=8)
#define BB 8
#define NN 4096
#define CC 512
#define GG 8
#define HH 8
#define DH 64
#define LL 512

// Scratch (device globals; no cudaMalloc allowed)
__device__ __half g_x_hi[(size_t)BB * NN * CC];        // [32768,512]
__device__ __half g_x_lo[(size_t)BB * NN * CC];
__device__ __half g_qkv_hi[(size_t)BB * NN * 3 * CC];  // [32768,1536]
__device__ __half g_qkv_lo[(size_t)BB * NN * 3 * CC];  // only Q cols (0..511) used
__device__ __half g_att_hi[(size_t)BB * NN * CC];      // [32768,512]
__device__ __half g_wq[(size_t)CC * 3 * CC];           // [512,1536] (K,N)
__device__ __half g_wp[(size_t)CC * CC];               // [512,512]

// ---------------------------------------------------------------------------
// Helpers
// ---------------------------------------------------------------------------
__device__ __forceinline__ uint32_t smem_u32(const void* p) {
    uint32_t a;
    asm("{ .reg .u64 t; cvta.to.shared.u64 t, %1; cvt.u32.u64 %0, t; }" : "=r"(a) : "l"(p));
    return a;
}

#define LDM_X4(r, a) \
    asm volatile("ldmatrix.sync.aligned.m8n8.x4.shared.b16 {%0,%1,%2,%3}, [%4];" \
        : "=r"((r)[0]), "=r"((r)[1]), "=r"((r)[2]), "=r"((r)[3]) : "r"(a))

#define LDM_X4T(r, a) \
    asm volatile("ldmatrix.sync.aligned.m8n8.x4.trans.shared.b16 {%0,%1,%2,%3}, [%4];" \
        : "=r"((r)[0]), "=r"((r)[1]), "=r"((r)[2]), "=r"((r)[3]) : "r"(a))

#define MMA16816(c, a, b0, b1) \
    asm volatile("mma.sync.aligned.m16n8k16.row.col.f32.f16.f16.f32 " \
        "{%0,%1,%2,%3}, {%4,%5,%6,%7}, {%8,%9}, {%0,%1,%2,%3};" \
        : "+f"((c)[0]), "+f"((c)[1]), "+f"((c)[2]), "+f"((c)[3]) \
        : "r"((a)[0]), "r"((a)[1]), "r"((a)[2]), "r"((a)[3]), "r"(b0), "r"(b1))

// .cg: bypass L1 (all staged data is single-read)
#define CP16(dst, src) \
    asm volatile("cp.async.cg.shared.global [%0], [%1], 16;" :: "r"(dst), "l"(src))
#define CP_COMMIT() asm volatile("cp.async.commit_group;")
#define CP_WAIT0() asm volatile("cp.async.wait_group 0;")
#define CP_WAIT1() asm volatile("cp.async.wait_group 1;")

__device__ __forceinline__ uint32_t pkh(__half2 v) {
    return *reinterpret_cast<uint32_t*>(&v);
}
__device__ __forceinline__ void split2h(float a, float b, uint32_t& hi, uint32_t& lo) {
    __half2 h = __floats2half2_rn(a, b);
    __half2 l = __floats2half2_rn(a - __half2float(h.x), b - __half2float(h.y));
    hi = pkh(h); lo = pkh(l);
}

// ---------------------------------------------------------------------------
// Weight round: fp32 -> fp16. x: fp32 -> fp16 hi/lo.
// ---------------------------------------------------------------------------
__global__ void roundw_kernel(const float* __restrict__ W,
                              __half* __restrict__ hi, int total) {
    int idx = blockIdx.x * blockDim.x + threadIdx.x;
    if (idx >= total) return;
    hi[idx] = __float2half_rn(W[idx]);
}

__global__ void splitx_kernel(const float* __restrict__ X,
                              __half* __restrict__ hi,
                              __half* __restrict__ lo) {
    int idx = blockIdx.x * blockDim.x + threadIdx.x;   // float4 index
    float4 v = *(const float4*)(X + (size_t)idx * 4);
    uint32_t h0, l0, h1, l1;
    split2h(v.x, v.y, h0, l0);
    split2h(v.z, v.w, h1, l1);
    uint2 hh; hh.x = h0; hh.y = h1;
    uint2 ll; ll.x = l0; ll.y = l1;
    *(uint2*)(hi + (size_t)idx * 4) = hh;
    *(uint2*)(lo + (size_t)idx * 4) = ll;
}

// ---------------------------------------------------------------------------
// fp16 HMMA GEMM, cp.async 2-stage pipeline, BK=64.
// C[:, n < two_ncols] = (Ah+Al) @ Bh   (2-term, precision-critical columns)
// C[:, n >= two_ncols] = Ah @ Bh       (1-term)
// Branch is CTA-uniform (n0 is per-CTA).
// ---------------------------------------------------------------------------
#define PSA 72
#define PSB 136
#define PS_AL 18432
#define PS_BH 36864
#define PSS   54272
#define PGSM_TOTAL (2 * PSS)     // 108544 -> 2 CTAs/SM

__global__ __launch_bounds__(256, 2) void gemm_h2_kernel(
    const __half* __restrict__ Ahi, const __half* __restrict__ Alo,
    const __half* __restrict__ Bh,
    const float* __restrict__ bias, float* __restrict__ C,
    __half* __restrict__ Chi, __half* __restrict__ Clo,
    int lo_ncols, int two_ncols,
    int M, int N, int K)
{
    extern __shared__ char sm[];
    const uint32_t sb = smem_u32(sm);
    const int tid = threadIdx.x;
    const int wid = tid >> 5, lane = tid & 31;
    const int wm = wid >> 2, wn = wid & 3;
    const int gid = lane >> 2, tig = lane & 3;
    const int m0 = blockIdx.y * 128, n0 = blockIdx.x * 128;
    const bool two = (n0 < two_ncols);   // CTA-uniform

    const int a_row = lane & 15;
    const int a_col = (lane >> 4) * 8;
    const int b_krow = lane & 15;
    const int b_ncol = (lane & 16) ? 8 : 0;

    const int ar = tid >> 3, aq = tid & 7;
    const int br = tid >> 4, bq = tid & 15;

    auto load_stage = [&](int c, int buf) {
        const uint32_t s0 = sb + buf * PSS;
        const int k0 = c * 64;
        #pragma unroll
        for (int i = 0; i < 4; ++i) {
            int r = ar + 32 * i;
            size_t ga = (size_t)(m0 + r) * K + k0 + aq * 8;
            uint32_t d = s0 + r * (PSA * 2) + aq * 16;
            CP16(d, Ahi + ga);
            if (two) CP16(d + PS_AL, Alo + ga);
        }
        #pragma unroll
        for (int i = 0; i < 4; ++i) {
            int r = br + 16 * i;
            size_t gb = (size_t)(k0 + r) * N + n0 + bq * 8;
            uint32_t d = s0 + PS_BH + r * (PSB * 2) + bq * 16;
            CP16(d, Bh + gb);
        }
        CP_COMMIT();
    };

    float acc[4][4][4];
    #pragma unroll
    for (int i = 0; i < 4; i++)
        #pragma unroll
        for (int j = 0; j < 4; j++)
            #pragma unroll
            for (int t = 0; t < 4; t++) acc[i][j][t] = 0.f;

    const int NC = K >> 6;
    load_stage(0, 0);

    for (int c = 0; c < NC; ++c) {
        if (c + 1 < NC) { load_stage(c + 1, (c + 1) & 1); CP_WAIT1(); }
        else            { CP_WAIT0(); }
        __syncthreads();

        const uint32_t s0 = sb + (c & 1) * PSS;
        #pragma unroll
        for (int ks = 0; ks < 4; ++ks) {
            uint32_t bh[2][4], af[4][4];
            #pragma unroll
            for (int p = 0; p < 2; ++p) {
                uint32_t ba = s0 + PS_BH
                    + (uint32_t)((ks * 16 + b_krow) * PSB + wn * 32 + p * 16 + b_ncol) * 2;
                LDM_X4T(bh[p], ba);
            }
            #pragma unroll
            for (int i = 0; i < 4; ++i) {
                uint32_t aa = s0
                    + (uint32_t)((wm * 64 + i * 16 + a_row) * PSA + ks * 16 + a_col) * 2;
                LDM_X4(af[i], aa);
            }
            #pragma unroll
            for (int i = 0; i < 4; ++i)
                #pragma unroll
                for (int j = 0; j < 4; ++j) {
                    int p = j >> 1, q2 = (j & 1) * 2;
                    MMA16816(acc[i][j], af[i], bh[p][q2], bh[p][q2 + 1]);
                }
            if (two) {
                #pragma unroll
                for (int i = 0; i < 4; ++i) {
                    uint32_t aa = s0 + PS_AL
                        + (uint32_t)((wm * 64 + i * 16 + a_row) * PSA + ks * 16 + a_col) * 2;
                    LDM_X4(af[i], aa);
                }
                #pragma unroll
                for (int i = 0; i < 4; ++i)
                    #pragma unroll
                    for (int j = 0; j < 4; ++j) {
                        int p = j >> 1, q2 = (j & 1) * 2;
                        MMA16816(acc[i][j], af[i], bh[p][q2], bh[p][q2 + 1]);
                    }
            }
        }
        __syncthreads();
    }

    #pragma unroll
    for (int i = 0; i < 4; ++i) {
        int r0 = m0 + wm * 64 + i * 16 + gid;
        #pragma unroll
        for (int j = 0; j < 4; ++j) {
            int cc = n0 + wn * 32 + j * 8 + 2 * tig;
            float bx = 0.f, by = 0.f;
            if (bias) { bx = bias[cc]; by = bias[cc + 1]; }
            float v0 = acc[i][j][0] + bx, v1 = acc[i][j][1] + by;
            float v2 = acc[i][j][2] + bx, v3 = acc[i][j][3] + by;
            if (Chi) {
                uint32_t h0, l0, h1, l1;
                split2h(v0, v1, h0, l0);
                split2h(v2, v3, h1, l1);
                *(uint32_t*)&Chi[(size_t)r0 * N + cc] = h0;
                *(uint32_t*)&Chi[(size_t)(r0 + 8) * N + cc] = h1;
                if (cc < lo_ncols) {
                    *(uint32_t*)&Clo[(size_t)r0 * N + cc] = l0;
                    *(uint32_t*)&Clo[(size_t)(r0 + 8) * N + cc] = l1;
                }
            } else {
                *(float2*)&C[(size_t)r0 * N + cc] = make_float2(v0, v1);
                *(float2*)&C[(size_t)(r0 + 8) * N + cc] = make_float2(v2, v3);
            }
        }
    }
}

// ---------------------------------------------------------------------------
// Tensorized flash attention, fp16:
// S = (Qh+Ql) Kh^T  (2-term),  O += Ph Vh  (1-term).
// Epilogue writes fp16 hi only (proj GEMM is 1-term now).
// ---------------------------------------------------------------------------
#define AT_QH 0
#define AT_QL 18432
#define AT_KV 36864
#define AT_KVB 18432
#define ATSM_TOTAL (AT_KV + 2 * AT_KVB)   // 73728

__global__ __launch_bounds__(256) void attn_mma_kernel()
{
    extern __shared__ char sm[];
    const uint32_t sb = smem_u32(sm);
    const int tid = threadIdx.x;
    const int w = tid >> 5, lane = tid & 31;
    const int gid = lane >> 2, tig = lane & 3;
    const int bgh = blockIdx.y;
    const int h = bgh & 7;
    const int g = (bgh >> 3) & 7;
    const int b = bgh >> 6;
    const int t0 = b * NN + g * LL;
    const int qrow0 = blockIdx.x * 128;
    const float scale = 0.125f;

    const int a_row = lane & 15;
    const int a_col = (lane >> 4) * 8;
    const int k_nrow = (lane & 7) + ((lane & 16) ? 8 : 0);
    const int k_kcol = (lane & 8) ? 8 : 0;
    const int v_krow = lane & 15;
    const int v_ncol = (lane & 16) ? 8 : 0;

    #pragma unroll
    for (int i = 0; i < 4; ++i) {
        int t = tid + 256 * i;
        int r = t >> 3, dq = t & 7;
        size_t go = (size_t)(t0 + qrow0 + r) * 1536 + h * 64 + dq * 8;
        uint32_t d = sb + AT_QH + r * 144 + dq * 16;
        CP16(d, g_qkv_hi + go);
        CP16(d + AT_QL, g_qkv_lo + go);
    }
    #pragma unroll
    for (int i = 0; i < 2; ++i) {
        int t = tid + 256 * i;
        int r = t >> 3, dq = t & 7;
        size_t go = (size_t)(t0 + r) * 1536 + 512 + h * 64 + dq * 8;
        uint32_t d = sb + AT_KV + r * 144 + dq * 16;
        CP16(d, g_qkv_hi + go);
        CP16(d + 9216, g_qkv_hi + go + 512);
    }
    CP_COMMIT();

    float s_o[8][4];
    float rmax0 = -1e30f, rmax1 = -1e30f, rsum0 = 0.f, rsum1 = 0.f;
    #pragma unroll
    for (int j = 0; j < 8; ++j)
        #pragma unroll
        for (int t = 0; t < 4; ++t) s_o[j][t] = 0.f;

    for (int c = 0; c < 8; ++c) {
        if (c < 7) {
            int buf = (c + 1) & 1;
            #pragma unroll
            for (int i = 0; i < 2; ++i) {
                int t = tid + 256 * i;
                int r = t >> 3, dq = t & 7;
                size_t go = (size_t)(t0 + (c + 1) * 64 + r) * 1536 + 512 + h * 64 + dq * 8;
                uint32_t d = sb + AT_KV + buf * AT_KVB + r * 144 + dq * 16;
                CP16(d, g_qkv_hi + go);
                CP16(d + 9216, g_qkv_hi + go + 512);
            }
            CP_COMMIT();
            CP_WAIT1();
        } else {
            CP_WAIT0();
        }
        __syncthreads();

        const uint32_t kb = sb + AT_KV + (c & 1) * AT_KVB;
        const uint32_t vb = kb + 9216;

        float s_[8][4];
        #pragma unroll
        for (int j = 0; j < 8; ++j)
            #pragma unroll
            for (int t = 0; t < 4; ++t) s_[j][t] = 0.f;

        #pragma unroll
        for (int ks = 0; ks < 4; ++ks) {
            uint32_t qh[4], ql[4], kh[4][4];
            uint32_t qa = sb + AT_QH + (uint32_t)((w * 16 + a_row) * 72 + ks * 16 + a_col) * 2;
            LDM_X4(qh, qa);
            LDM_X4(ql, qa + AT_QL);
            #pragma unroll
            for (int p = 0; p < 4; ++p) {
                uint32_t ka = kb + (uint32_t)((p * 16 + k_nrow) * 72 + ks * 16 + k_kcol) * 2;
                LDM_X4(kh[p], ka);
            }
            #pragma unroll
            for (int j = 0; j < 8; ++j) {
                int p = j >> 1, q2 = (j & 1) * 2;
                MMA16816(s_[j], qh, kh[p][q2], kh[p][q2 + 1]);
                MMA16816(s_[j], ql, kh[p][q2], kh[p][q2 + 1]);
            }
        }

        float m0 = -1e30f, m1 = -1e30f;
        #pragma unroll
        for (int j = 0; j < 8; ++j) {
            s_[j][0] *= scale; s_[j][1] *= scale;
            s_[j][2] *= scale; s_[j][3] *= scale;
            m0 = fmaxf(m0, fmaxf(s_[j][0], s_[j][1]));
            m1 = fmaxf(m1, fmaxf(s_[j][2], s_[j][3]));
        }
        m0 = fmaxf(m0, __shfl_xor_sync(0xffffffffu, m0, 1));
        m0 = fmaxf(m0, __shfl_xor_sync(0xffffffffu, m0, 2));
        m1 = fmaxf(m1, __shfl_xor_sync(0xffffffffu, m1, 1));
        m1 = fmaxf(m1, __shfl_xor_sync(0xffffffffu, m1, 2));
        float nm0 = fmaxf(rmax0, m0), nm1 = fmaxf(rmax1, m1);
        float al0 = __expf(rmax0 - nm0), al1 = __expf(rmax1 - nm1);
        float cs0 = 0.f, cs1 = 0.f;
        #pragma unroll
        for (int j = 0; j < 8; ++j) {
            s_[j][0] = __expf(s_[j][0] - nm0);
            s_[j][1] = __expf(s_[j][1] - nm0);
            s_[j][2] = __expf(s_[j][2] - nm1);
            s_[j][3] = __expf(s_[j][3] - nm1);
            cs0 += s_[j][0] + s_[j][1];
            cs1 += s_[j][2] + s_[j][3];
        }
        cs0 += __shfl_xor_sync(0xffffffffu, cs0, 1);
        cs0 += __shfl_xor_sync(0xffffffffu, cs0, 2);
        cs1 += __shfl_xor_sync(0xffffffffu, cs1, 1);
        cs1 += __shfl_xor_sync(0xffffffffu, cs1, 2);
        rsum0 = rsum0 * al0 + cs0;
        rsum1 = rsum1 * al1 + cs1;
        rmax0 = nm0; rmax1 = nm1;
        #pragma unroll
        for (int j = 0; j < 8; ++j) {
            s_o[j][0] *= al0; s_o[j][1] *= al0;
            s_o[j][2] *= al1; s_o[j][3] *= al1;
        }

        #pragma unroll
        for (int kf = 0; kf < 4; ++kf) {
            uint32_t ph[4], vh[4][4];
            int ja = 2 * kf, jb = 2 * kf + 1;
            ph[0] = pkh(__floats2half2_rn(s_[ja][0], s_[ja][1]));
            ph[1] = pkh(__floats2half2_rn(s_[ja][2], s_[ja][3]));
            ph[2] = pkh(__floats2half2_rn(s_[jb][0], s_[jb][1]));
            ph[3] = pkh(__floats2half2_rn(s_[jb][2], s_[jb][3]));
            #pragma unroll
            for (int p = 0; p < 4; ++p) {
                uint32_t va = vb + (uint32_t)((kf * 16 + v_krow) * 72 + p * 16 + v_ncol) * 2;
                LDM_X4T(vh[p], va);
            }
            #pragma unroll
            for (int j = 0; j < 8; ++j) {
                int p = j >> 1, q2 = (j & 1) * 2;
                MMA16816(s_o[j], ph, vh[p][q2], vh[p][q2 + 1]);
            }
        }
        __syncthreads();
    }

    // normalize + write fp16 hi only
    float inv0 = 1.f / rsum0, inv1 = 1.f / rsum1;
    const int r0 = t0 + qrow0 + w * 16 + gid;
    #pragma unroll
    for (int j = 0; j < 8; ++j) {
        int cc = h * 64 + j * 8 + 2 * tig;
        *(uint32_t*)&g_att_hi[(size_t)r0 * CC + cc] =
            pkh(__floats2half2_rn(s_o[j][0] * inv0, s_o[j][1] * inv0));
        *(uint32_t*)&g_att_hi[(size_t)(r0 + 8) * CC + cc] =
            pkh(__floats2half2_rn(s_o[j][2] * inv1, s_o[j][3] * inv1));
    }
}

// ---------------------------------------------------------------------------
extern "C" void kernel_launch(void* const* d_in, const int* in_sizes, int n_in,
                              void* d_out, int out_size)
{
    const float* x      = (const float*)d_in[0];
    const float* W_qkv  = (const float*)d_in[1];
    const float* W_proj = (const float*)d_in[2];
    const float* b_proj = (const float*)d_in[3];
    float* out = (float*)d_out;

    __half *xh, *xl, *qkvh, *qkvl, *ath, *wq, *wp;
    cudaGetSymbolAddress((void**)&xh, g_x_hi);
    cudaGetSymbolAddress((void**)&xl, g_x_lo);
    cudaGetSymbolAddress((void**)&qkvh, g_qkv_hi);
    cudaGetSymbolAddress((void**)&qkvl, g_qkv_lo);
    cudaGetSymbolAddress((void**)&ath, g_att_hi);
    cudaGetSymbolAddress((void**)&wq, g_wq);
    cudaGetSymbolAddress((void**)&wp, g_wp);

    cudaFuncSetAttribute(gemm_h2_kernel,
                         cudaFuncAttributeMaxDynamicSharedMemorySize, PGSM_TOTAL);
    cudaFuncSetAttribute(attn_mma_kernel,
                         cudaFuncAttributeMaxDynamicSharedMemorySize, ATSM_TOTAL);

    const int M = BB * NN;   // 32768

    // 0) Weight round (fp16 single) + x split (fp16 hi/lo)
    roundw_kernel<<<(3 * CC * CC + 255) / 256, 256>>>(W_qkv, wq, 3 * CC * CC);
    roundw_kernel<<<(CC * CC + 255) / 256, 256>>>(W_proj, wp, CC * CC);
    splitx_kernel<<<(M * CC / 4) / 256, 256>>>(x, xh, xl);

    // 1) qkv = x @ W_qkv: Q cols 2-term (x hi+lo), K/V cols 1-term.
    {
        dim3 grid((3 * CC) / 128, M / 128);
        gemm_h2_kernel<<<grid, 256, PGSM_TOTAL>>>(xh, xl, wq, nullptr,
                                                  nullptr, qkvh, qkvl,
                                                  CC /*lo_ncols*/, CC /*two_ncols*/,
                                                  M, 3 * CC, CC);
    }

    // 2) tensorized flash attention -> fp16 hi out
    {
        dim3 grid(LL / 128, BB * GG * HH);
        attn_mma_kernel<<<grid, 256, ATSM_TOTAL>>>();
    }

    // 3) out = att @ W_proj + b_proj: pure 1-term fp16, fp32 out.
    {
        dim3 grid(CC / 128, M / 128);
        gemm_h2_kernel<<<grid, 256, PGSM_TOTAL>>>(ath, ath /*unused*/, wp, b_proj,
                                                  out, nullptr, nullptr,
                                                  0 /*lo_ncols*/, 0 /*two_ncols*/,
                                                  M, CC, CC);
    }
}

// round 12
// speedup vs baseline: 2.5212x; 1.2381x over previous
#include <cuda_runtime.h>
#include <cuda_fp16.h>
#include <math.h>
#include <stdint.h>

// Problem constants (recursive_index=0 -> G=8)
#define BB 8
#define NN 4096
#define CC 512
#define GG 8
#define HH 8
#define DH 64
#define LL 512

// Scratch (device globals; no cudaMalloc allowed)
__device__ __half g_x[(size_t)BB * NN * CC];          // [32768,512] fp16
__device__ __half g_qkv[(size_t)BB * NN * 3 * CC];    // [32768,1536] fp16
__device__ __half g_att[(size_t)BB * NN * CC];        // [32768,512] fp16
__device__ __half g_wq[(size_t)CC * 3 * CC];          // [512,1536] (K,N)
__device__ __half g_wp[(size_t)CC * CC];              // [512,512]

// ---------------------------------------------------------------------------
// Helpers
// ---------------------------------------------------------------------------
__device__ __forceinline__ uint32_t smem_u32(const void* p) {
    uint32_t a;
    asm("{ .reg .u64 t; cvta.to.shared.u64 t, %1; cvt.u32.u64 %0, t; }" : "=r"(a) : "l"(p));
    return a;
}

#define LDM_X4(r, a) \
    asm volatile("ldmatrix.sync.aligned.m8n8.x4.shared.b16 {%0,%1,%2,%3}, [%4];" \
        : "=r"((r)[0]), "=r"((r)[1]), "=r"((r)[2]), "=r"((r)[3]) : "r"(a))

#define LDM_X4T(r, a) \
    asm volatile("ldmatrix.sync.aligned.m8n8.x4.trans.shared.b16 {%0,%1,%2,%3}, [%4];" \
        : "=r"((r)[0]), "=r"((r)[1]), "=r"((r)[2]), "=r"((r)[3]) : "r"(a))

#define MMA16816(c, a, b0, b1) \
    asm volatile("mma.sync.aligned.m16n8k16.row.col.f32.f16.f16.f32 " \
        "{%0,%1,%2,%3}, {%4,%5,%6,%7}, {%8,%9}, {%0,%1,%2,%3};" \
        : "+f"((c)[0]), "+f"((c)[1]), "+f"((c)[2]), "+f"((c)[3]) \
        : "r"((a)[0]), "r"((a)[1]), "r"((a)[2]), "r"((a)[3]), "r"(b0), "r"(b1))

// .cg: bypass L1 (all staged data is single-read)
#define CP16(dst, src) \
    asm volatile("cp.async.cg.shared.global [%0], [%1], 16;" :: "r"(dst), "l"(src))
#define CP_COMMIT() asm volatile("cp.async.commit_group;")
#define CP_WAIT0() asm volatile("cp.async.wait_group 0;")
#define CP_WAIT1() asm volatile("cp.async.wait_group 1;")

__device__ __forceinline__ uint32_t pkh(__half2 v) {
    return *reinterpret_cast<uint32_t*>(&v);
}

// ---------------------------------------------------------------------------
// Round fp32 -> fp16 (vectorized float4 -> half2x2)
// ---------------------------------------------------------------------------
__global__ void roundv_kernel(const float* __restrict__ X,
                              __half* __restrict__ H) {
    int idx = blockIdx.x * blockDim.x + threadIdx.x;   // float4 index
    float4 v = *(const float4*)(X + (size_t)idx * 4);
    uint2 hh;
    hh.x = pkh(__floats2half2_rn(v.x, v.y));
    hh.y = pkh(__floats2half2_rn(v.z, v.w));
    *(uint2*)(H + (size_t)idx * 4) = hh;
}

// ---------------------------------------------------------------------------
// Pure fp16 HMMA GEMM (fp32 accum), cp.async 2-stage pipeline, BK=64.
// C[M,N] = A[M,K] @ B[K,N] (+bias). Output fp32 C or fp16 Ch.
// CTA 128x128, 8 warps (2x4 of 64x32).
// Stage layout (bytes, fp16 row strides: A 72, B 136):
//   A 0..18432, B 18432..35840
// ---------------------------------------------------------------------------
#define PSA 72
#define PSB 136
#define PS_B 18432
#define PSS   35840
#define PGSM_TOTAL (2 * PSS)     // 71680 -> 2 CTAs/SM

__global__ __launch_bounds__(256, 2) void gemm_h1_kernel(
    const __half* __restrict__ A, const __half* __restrict__ B,
    const float* __restrict__ bias, float* __restrict__ C,
    __half* __restrict__ Ch,
    int M, int N, int K)
{
    extern __shared__ char sm[];
    const uint32_t sb = smem_u32(sm);
    const int tid = threadIdx.x;
    const int wid = tid >> 5, lane = tid & 31;
    const int wm = wid >> 2, wn = wid & 3;
    const int gid = lane >> 2, tig = lane & 3;
    const int m0 = blockIdx.y * 128, n0 = blockIdx.x * 128;

    const int a_row = lane & 15;
    const int a_col = (lane >> 4) * 8;
    const int b_krow = lane & 15;
    const int b_ncol = (lane & 16) ? 8 : 0;

    const int ar = tid >> 3, aq = tid & 7;
    const int br = tid >> 4, bq = tid & 15;

    auto load_stage = [&](int c, int buf) {
        const uint32_t s0 = sb + buf * PSS;
        const int k0 = c * 64;
        #pragma unroll
        for (int i = 0; i < 4; ++i) {
            int r = ar + 32 * i;
            size_t ga = (size_t)(m0 + r) * K + k0 + aq * 8;
            CP16(s0 + r * (PSA * 2) + aq * 16, A + ga);
        }
        #pragma unroll
        for (int i = 0; i < 4; ++i) {
            int r = br + 16 * i;
            size_t gb = (size_t)(k0 + r) * N + n0 + bq * 8;
            CP16(s0 + PS_B + r * (PSB * 2) + bq * 16, B + gb);
        }
        CP_COMMIT();
    };

    float acc[4][4][4];
    #pragma unroll
    for (int i = 0; i < 4; i++)
        #pragma unroll
        for (int j = 0; j < 4; j++)
            #pragma unroll
            for (int t = 0; t < 4; t++) acc[i][j][t] = 0.f;

    const int NC = K >> 6;
    load_stage(0, 0);

    for (int c = 0; c < NC; ++c) {
        if (c + 1 < NC) { load_stage(c + 1, (c + 1) & 1); CP_WAIT1(); }
        else            { CP_WAIT0(); }
        __syncthreads();

        const uint32_t s0 = sb + (c & 1) * PSS;
        #pragma unroll
        for (int ks = 0; ks < 4; ++ks) {
            uint32_t bh[2][4], af[4][4];
            #pragma unroll
            for (int p = 0; p < 2; ++p) {
                uint32_t ba = s0 + PS_B
                    + (uint32_t)((ks * 16 + b_krow) * PSB + wn * 32 + p * 16 + b_ncol) * 2;
                LDM_X4T(bh[p], ba);
            }
            #pragma unroll
            for (int i = 0; i < 4; ++i) {
                uint32_t aa = s0
                    + (uint32_t)((wm * 64 + i * 16 + a_row) * PSA + ks * 16 + a_col) * 2;
                LDM_X4(af[i], aa);
            }
            #pragma unroll
            for (int i = 0; i < 4; ++i)
                #pragma unroll
                for (int j = 0; j < 4; ++j) {
                    int p = j >> 1, q2 = (j & 1) * 2;
                    MMA16816(acc[i][j], af[i], bh[p][q2], bh[p][q2 + 1]);
                }
        }
        __syncthreads();
    }

    #pragma unroll
    for (int i = 0; i < 4; ++i) {
        int r0 = m0 + wm * 64 + i * 16 + gid;
        #pragma unroll
        for (int j = 0; j < 4; ++j) {
            int cc = n0 + wn * 32 + j * 8 + 2 * tig;
            float bx = 0.f, by = 0.f;
            if (bias) { bx = bias[cc]; by = bias[cc + 1]; }
            float v0 = acc[i][j][0] + bx, v1 = acc[i][j][1] + by;
            float v2 = acc[i][j][2] + bx, v3 = acc[i][j][3] + by;
            if (Ch) {
                *(uint32_t*)&Ch[(size_t)r0 * N + cc] = pkh(__floats2half2_rn(v0, v1));
                *(uint32_t*)&Ch[(size_t)(r0 + 8) * N + cc] = pkh(__floats2half2_rn(v2, v3));
            } else {
                *(float2*)&C[(size_t)r0 * N + cc] = make_float2(v0, v1);
                *(float2*)&C[(size_t)(r0 + 8) * N + cc] = make_float2(v2, v3);
            }
        }
    }
}

// ---------------------------------------------------------------------------
// Tensorized flash attention, pure fp16 (fp32 accum):
// S = Q K^T (1-term),  O += P V (1-term).
// Smem: Q [128][72]@0 (18432); KV double-buffered @18432,
//   per buffer (18432B): K [64][72] @+0, V [64][72] @+9216.
// ---------------------------------------------------------------------------
#define AT_KV 18432
#define AT_KVB 18432
#define ATSM_TOTAL (AT_KV + 2 * AT_KVB)   // 55296

__global__ __launch_bounds__(256) void attn_mma_kernel()
{
    extern __shared__ char sm[];
    const uint32_t sb = smem_u32(sm);
    const int tid = threadIdx.x;
    const int w = tid >> 5, lane = tid & 31;
    const int gid = lane >> 2, tig = lane & 3;
    const int bgh = blockIdx.y;
    const int h = bgh & 7;
    const int g = (bgh >> 3) & 7;
    const int b = bgh >> 6;
    const int t0 = b * NN + g * LL;
    const int qrow0 = blockIdx.x * 128;
    const float scale = 0.125f;

    const int a_row = lane & 15;
    const int a_col = (lane >> 4) * 8;
    const int k_nrow = (lane & 7) + ((lane & 16) ? 8 : 0);
    const int k_kcol = (lane & 8) ? 8 : 0;
    const int v_krow = lane & 15;
    const int v_ncol = (lane & 16) ? 8 : 0;

    // Q: 128 rows x 64 fp16 = 8 x 16B per row (1024 cp / 256 thr = 4 iters)
    #pragma unroll
    for (int i = 0; i < 4; ++i) {
        int t = tid + 256 * i;
        int r = t >> 3, dq = t & 7;
        size_t go = (size_t)(t0 + qrow0 + r) * 1536 + h * 64 + dq * 8;
        CP16(sb + r * 144 + dq * 16, g_qkv + go);
    }
    // KV chunk 0
    #pragma unroll
    for (int i = 0; i < 2; ++i) {
        int t = tid + 256 * i;
        int r = t >> 3, dq = t & 7;
        size_t go = (size_t)(t0 + r) * 1536 + 512 + h * 64 + dq * 8;
        uint32_t d = sb + AT_KV + r * 144 + dq * 16;
        CP16(d, g_qkv + go);             // K
        CP16(d + 9216, g_qkv + go + 512); // V
    }
    CP_COMMIT();

    float s_o[8][4];
    float rmax0 = -1e30f, rmax1 = -1e30f, rsum0 = 0.f, rsum1 = 0.f;
    #pragma unroll
    for (int j = 0; j < 8; ++j)
        #pragma unroll
        for (int t = 0; t < 4; ++t) s_o[j][t] = 0.f;

    for (int c = 0; c < 8; ++c) {
        if (c < 7) {
            int buf = (c + 1) & 1;
            #pragma unroll
            for (int i = 0; i < 2; ++i) {
                int t = tid + 256 * i;
                int r = t >> 3, dq = t & 7;
                size_t go = (size_t)(t0 + (c + 1) * 64 + r) * 1536 + 512 + h * 64 + dq * 8;
                uint32_t d = sb + AT_KV + buf * AT_KVB + r * 144 + dq * 16;
                CP16(d, g_qkv + go);
                CP16(d + 9216, g_qkv + go + 512);
            }
            CP_COMMIT();
            CP_WAIT1();
        } else {
            CP_WAIT0();
        }
        __syncthreads();

        const uint32_t kb = sb + AT_KV + (c & 1) * AT_KVB;
        const uint32_t vb = kb + 9216;

        float s_[8][4];
        #pragma unroll
        for (int j = 0; j < 8; ++j)
            #pragma unroll
            for (int t = 0; t < 4; ++t) s_[j][t] = 0.f;

        #pragma unroll
        for (int ks = 0; ks < 4; ++ks) {
            uint32_t qh[4], kh[4][4];
            uint32_t qa = sb + (uint32_t)((w * 16 + a_row) * 72 + ks * 16 + a_col) * 2;
            LDM_X4(qh, qa);
            #pragma unroll
            for (int p = 0; p < 4; ++p) {
                uint32_t ka = kb + (uint32_t)((p * 16 + k_nrow) * 72 + ks * 16 + k_kcol) * 2;
                LDM_X4(kh[p], ka);
            }
            #pragma unroll
            for (int j = 0; j < 8; ++j) {
                int p = j >> 1, q2 = (j & 1) * 2;
                MMA16816(s_[j], qh, kh[p][q2], kh[p][q2 + 1]);
            }
        }

        float m0 = -1e30f, m1 = -1e30f;
        #pragma unroll
        for (int j = 0; j < 8; ++j) {
            s_[j][0] *= scale; s_[j][1] *= scale;
            s_[j][2] *= scale; s_[j][3] *= scale;
            m0 = fmaxf(m0, fmaxf(s_[j][0], s_[j][1]));
            m1 = fmaxf(m1, fmaxf(s_[j][2], s_[j][3]));
        }
        m0 = fmaxf(m0, __shfl_xor_sync(0xffffffffu, m0, 1));
        m0 = fmaxf(m0, __shfl_xor_sync(0xffffffffu, m0, 2));
        m1 = fmaxf(m1, __shfl_xor_sync(0xffffffffu, m1, 1));
        m1 = fmaxf(m1, __shfl_xor_sync(0xffffffffu, m1, 2));
        float nm0 = fmaxf(rmax0, m0), nm1 = fmaxf(rmax1, m1);
        float al0 = __expf(rmax0 - nm0), al1 = __expf(rmax1 - nm1);
        float cs0 = 0.f, cs1 = 0.f;
        #pragma unroll
        for (int j = 0; j < 8; ++j) {
            s_[j][0] = __expf(s_[j][0] - nm0);
            s_[j][1] = __expf(s_[j][1] - nm0);
            s_[j][2] = __expf(s_[j][2] - nm1);
            s_[j][3] = __expf(s_[j][3] - nm1);
            cs0 += s_[j][0] + s_[j][1];
            cs1 += s_[j][2] + s_[j][3];
        }
        cs0 += __shfl_xor_sync(0xffffffffu, cs0, 1);
        cs0 += __shfl_xor_sync(0xffffffffu, cs0, 2);
        cs1 += __shfl_xor_sync(0xffffffffu, cs1, 1);
        cs1 += __shfl_xor_sync(0xffffffffu, cs1, 2);
        rsum0 = rsum0 * al0 + cs0;
        rsum1 = rsum1 * al1 + cs1;
        rmax0 = nm0; rmax1 = nm1;
        #pragma unroll
        for (int j = 0; j < 8; ++j) {
            s_o[j][0] *= al0; s_o[j][1] *= al0;
            s_o[j][2] *= al1; s_o[j][3] *= al1;
        }

        #pragma unroll
        for (int kf = 0; kf < 4; ++kf) {
            uint32_t ph[4], vh[4][4];
            int ja = 2 * kf, jb = 2 * kf + 1;
            ph[0] = pkh(__floats2half2_rn(s_[ja][0], s_[ja][1]));
            ph[1] = pkh(__floats2half2_rn(s_[ja][2], s_[ja][3]));
            ph[2] = pkh(__floats2half2_rn(s_[jb][0], s_[jb][1]));
            ph[3] = pkh(__floats2half2_rn(s_[jb][2], s_[jb][3]));
            #pragma unroll
            for (int p = 0; p < 4; ++p) {
                uint32_t va = vb + (uint32_t)((kf * 16 + v_krow) * 72 + p * 16 + v_ncol) * 2;
                LDM_X4T(vh[p], va);
            }
            #pragma unroll
            for (int j = 0; j < 8; ++j) {
                int p = j >> 1, q2 = (j & 1) * 2;
                MMA16816(s_o[j], ph, vh[p][q2], vh[p][q2 + 1]);
            }
        }
        __syncthreads();
    }

    // normalize + write fp16
    float inv0 = 1.f / rsum0, inv1 = 1.f / rsum1;
    const int r0 = t0 + qrow0 + w * 16 + gid;
    #pragma unroll
    for (int j = 0; j < 8; ++j) {
        int cc = h * 64 + j * 8 + 2 * tig;
        *(uint32_t*)&g_att[(size_t)r0 * CC + cc] =
            pkh(__floats2half2_rn(s_o[j][0] * inv0, s_o[j][1] * inv0));
        *(uint32_t*)&g_att[(size_t)(r0 + 8) * CC + cc] =
            pkh(__floats2half2_rn(s_o[j][2] * inv1, s_o[j][3] * inv1));
    }
}

// ---------------------------------------------------------------------------
extern "C" void kernel_launch(void* const* d_in, const int* in_sizes, int n_in,
                              void* d_out, int out_size)
{
    const float* x      = (const float*)d_in[0];
    const float* W_qkv  = (const float*)d_in[1];
    const float* W_proj = (const float*)d_in[2];
    const float* b_proj = (const float*)d_in[3];
    float* out = (float*)d_out;

    __half *xh, *qkvh, *ath, *wq, *wp;
    cudaGetSymbolAddress((void**)&xh, g_x);
    cudaGetSymbolAddress((void**)&qkvh, g_qkv);
    cudaGetSymbolAddress((void**)&ath, g_att);
    cudaGetSymbolAddress((void**)&wq, g_wq);
    cudaGetSymbolAddress((void**)&wp, g_wp);

    cudaFuncSetAttribute(gemm_h1_kernel,
                         cudaFuncAttributeMaxDynamicSharedMemorySize, PGSM_TOTAL);
    cudaFuncSetAttribute(attn_mma_kernel,
                         cudaFuncAttributeMaxDynamicSharedMemorySize, ATSM_TOTAL);

    const int M = BB * NN;   // 32768

    // 0) Round inputs/weights to fp16 (vectorized; totals are /4 divisible)
    roundv_kernel<<<(3 * CC * CC / 4) / 256, 256>>>(W_qkv, wq);
    roundv_kernel<<<(CC * CC / 4) / 256, 256>>>(W_proj, wp);
    roundv_kernel<<<((size_t)M * CC / 4) / 256, 256>>>(x, xh);

    // 1) qkv = x @ W_qkv  (pure fp16, fp32 accum), fp16 out
    {
        dim3 grid((3 * CC) / 128, M / 128);
        gemm_h1_kernel<<<grid, 256, PGSM_TOTAL>>>(xh, wq, nullptr,
                                                  nullptr, qkvh,
                                                  M, 3 * CC, CC);
    }

    // 2) tensorized flash attention (pure fp16) -> fp16 out
    {
        dim3 grid(LL / 128, BB * GG * HH);
        attn_mma_kernel<<<grid, 256, ATSM_TOTAL>>>();
    }

    // 3) out = att @ W_proj + b_proj  (pure fp16), fp32 out
    {
        dim3 grid(CC / 128, M / 128);
        gemm_h1_kernel<<<grid, 256, PGSM_TOTAL>>>(ath, wp, b_proj,
                                                  out, nullptr,
                                                  M, CC, CC);
    }
}